// round 13
// baseline (speedup 1.0000x reference)
#include <cuda_runtime.h>
#include <cuda_fp16.h>
#include <math.h>
#include <cstdint>

// Problem constants
#define S_LEN 2048
#define HDIM  2048
#define NHQ   16
#define NHKV  4
#define HD    128
#define BATCH 2
#define M_ROWS (BATCH * S_LEN)   // 4096
#define NQKV  3072               // 2048 (Q) + 512 (K) + 512 (V)

// ---------------------------------------------------------------------------
// Scratch (allocation-free: __device__ globals)
// ---------------------------------------------------------------------------
__device__ float g_q[BATCH * NHQ * S_LEN * HD];     // fp32 pre-RoPE Q
__device__ float g_k[BATCH * NHKV * S_LEN * HD];

__device__ __half g_x16[M_ROWS * HDIM];             // hidden fp16
__device__ __half g_wqkv16[NQKV * HDIM];            // concat Wq|Wk|Wv fp16
__device__ __half g_wo16[HDIM * HDIM];
__device__ float  g_bqkv[NQKV];                     // concat bq|bk|bv
__device__ __half g_qh16[BATCH * NHQ * S_LEN * HD];   // post-RoPE Q (scaled)
__device__ __half g_kh16[BATCH * NHKV * S_LEN * HD];  // post-RoPE K
__device__ __half g_vh16[BATCH * NHKV * S_LEN * HD];  // V fp16 (direct)
__device__ __half g_a16[M_ROWS * HDIM];               // attn out, row-major

// ---------------------------------------------------------------------------
// PTX helpers
// ---------------------------------------------------------------------------
__device__ __forceinline__ uint32_t smem_to_u32(const void* smem_ptr) {
    uint32_t addr;
    asm("{ .reg .u64 tmp; cvta.to.shared.u64 tmp, %1; cvt.u32.u64 %0, tmp; }"
        : "=r"(addr) : "l"(smem_ptr));
    return addr;
}

__device__ __forceinline__ void ldsm_x4(uint32_t* r, uint32_t addr) {
    asm volatile("ldmatrix.sync.aligned.m8n8.x4.shared.b16 {%0,%1,%2,%3}, [%4];"
                 : "=r"(r[0]), "=r"(r[1]), "=r"(r[2]), "=r"(r[3]) : "r"(addr));
}

__device__ __forceinline__ void ldsm_x4_trans(uint32_t* r, uint32_t addr) {
    asm volatile("ldmatrix.sync.aligned.m8n8.x4.trans.shared.b16 {%0,%1,%2,%3}, [%4];"
                 : "=r"(r[0]), "=r"(r[1]), "=r"(r[2]), "=r"(r[3]) : "r"(addr));
}

__device__ __forceinline__ void mma16816(float* d, const uint32_t* a,
                                         const uint32_t* b) {
    asm volatile(
        "mma.sync.aligned.m16n8k16.row.col.f32.f16.f16.f32 "
        "{%0,%1,%2,%3}, {%4,%5,%6,%7}, {%8,%9}, {%0,%1,%2,%3};"
        : "+f"(d[0]), "+f"(d[1]), "+f"(d[2]), "+f"(d[3])
        : "r"(a[0]), "r"(a[1]), "r"(a[2]), "r"(a[3]), "r"(b[0]), "r"(b[1]));
}

#define CP_ASYNC16(dst_u32, src_ptr) \
    asm volatile("cp.async.cg.shared.global [%0], [%1], 16;" \
                 :: "r"(dst_u32), "l"(src_ptr))
#define CP_COMMIT() asm volatile("cp.async.commit_group;" ::: "memory")
#define CP_WAIT(n)  asm volatile("cp.async.wait_group %0;" :: "n"(n) : "memory")

__device__ __forceinline__ uint32_t pack_h2(float x, float y) {
    __half2 t = __floats2half2_rn(x, y);
    return *(uint32_t*)&t;
}

// ---------------------------------------------------------------------------
// Merged fp32 -> fp16 conversion over all 5 tensors (one launch).
// f4-index regions: [0,N0)=x, [N0,N1)=wq, [N1,N2)=wk, [N2,N3)=wv, [N3,N4)=wo
// ---------------------------------------------------------------------------
#define CV_N0 (M_ROWS * HDIM / 4)
#define CV_N1 (CV_N0 + HDIM * HDIM / 4)
#define CV_N2 (CV_N1 + 512 * HDIM / 4)
#define CV_N3 (CV_N2 + 512 * HDIM / 4)
#define CV_N4 (CV_N3 + HDIM * HDIM / 4)

__device__ __forceinline__ void cvt4(const float* __restrict__ in,
                                     __half* __restrict__ out, int j)
{
    float4 v = ((const float4*)in)[j];
    ((__half2*)out)[2 * j]     = __floats2half2_rn(v.x, v.y);
    ((__half2*)out)[2 * j + 1] = __floats2half2_rn(v.z, v.w);
}

__global__ void cvt_all_kernel(const float* __restrict__ hs,
                               const float* __restrict__ wq,
                               const float* __restrict__ wk,
                               const float* __restrict__ wv,
                               const float* __restrict__ wo,
                               __half* __restrict__ x16,
                               __half* __restrict__ wqkv16,
                               __half* __restrict__ wo16)
{
    int i = blockIdx.x * 256 + threadIdx.x;
    if (i < CV_N0)      cvt4(hs, x16, i);
    else if (i < CV_N1) cvt4(wq, wqkv16, i - CV_N0);
    else if (i < CV_N2) cvt4(wk, wqkv16 + 2048 * HDIM, i - CV_N1);
    else if (i < CV_N3) cvt4(wv, wqkv16 + 2560 * HDIM, i - CV_N2);
    else if (i < CV_N4) cvt4(wo, wo16, i - CV_N3);
}

// ---------------------------------------------------------------------------
// GEMM core: block 128x128, BK=32, 4 warps (2m x 2n), warp tile 64x64,
// 128 threads, 4-stage cp.async pipeline. MMA:ldsm ratio 4.0.
// ---------------------------------------------------------------------------
#define MATB (128 * 80)              // 10240 B per matrix tile
#define STAGEB (2 * MATB)            // A + B = 20480 B
#define NSTAGE 4
#define GEMM_SMEM (NSTAGE * STAGEB)  // 81920 B
#define GEMM_THREADS 128

__device__ __forceinline__ void gemm_copy_stage(
    uint32_t s_u32,
    const __half* __restrict__ Ap, const __half* __restrict__ Bp,
    int m0, int n0, int k0, int Kdim, int t)
{
#pragma unroll
    for (int i = 0; i < 4; i++) {
        int chunk = t + i * GEMM_THREADS;      // 0..511
        int row = chunk >> 2;
        int ch  = chunk & 3;
        uint32_t dst = s_u32 + row * 80 + ch * 16;
        size_t aoff = (size_t)(m0 + row) * Kdim + k0 + ch * 8;
        size_t boff = (size_t)(n0 + row) * Kdim + k0 + ch * 8;
        CP_ASYNC16(dst,        Ap + aoff);
        CP_ASYNC16(dst + MATB, Bp + boff);
    }
}

// Mainloop: fills acc[4][8][4] (warp tile 64x64).
__device__ __forceinline__ void gemm_mainloop(
    uint32_t s_u32, const __half* Ap, const __half* Bp,
    int m0, int n0, int Kdim, int t, int lane,
    int wm, int wn, float acc[4][8][4])
{
    const int nsteps = Kdim >> 5;
    const int a_row_l = lane & 15;
    const int a_col_l = (lane >> 4) * 8;
    const int b_row_l = ((lane >> 4) << 3) + (lane & 7);
    const int b_col_l = ((lane >> 3) & 1) * 8;

    // Prologue: stages 0..2
#pragma unroll
    for (int s = 0; s < NSTAGE - 1; s++) {
        gemm_copy_stage(s_u32 + s * STAGEB, Ap, Bp, m0, n0, s * 32, Kdim, t);
        CP_COMMIT();
    }

    int buf = 0;
    for (int s = 0; s < nsteps; s++) {
        if (s + 2 < nsteps)      { CP_WAIT(2); }
        else if (s + 1 < nsteps) { CP_WAIT(1); }
        else                     { CP_WAIT(0); }
        __syncthreads();

        if (s + NSTAGE - 1 < nsteps) {
            int nb = buf + NSTAGE - 1; if (nb >= NSTAGE) nb -= NSTAGE;
            gemm_copy_stage(s_u32 + nb * STAGEB, Ap, Bp,
                            m0, n0, (s + NSTAGE - 1) << 5, Kdim, t);
            CP_COMMIT();
        }

        uint32_t sA = s_u32 + buf * STAGEB;
        uint32_t sB = sA + MATB;

#pragma unroll
        for (int kh = 0; kh < 2; kh++) {
            uint32_t af[4][4], bf[4][4];
#pragma unroll
            for (int mt = 0; mt < 4; mt++) {
                uint32_t ad = sA + (wm + mt * 16 + a_row_l) * 80 +
                              (kh * 16 + a_col_l) * 2;
                ldsm_x4(af[mt], ad);
            }
#pragma unroll
            for (int np = 0; np < 4; np++) {
                uint32_t bd = sB + (wn + np * 16 + b_row_l) * 80 +
                              (kh * 16 + b_col_l) * 2;
                ldsm_x4(bf[np], bd);
            }
#pragma unroll
            for (int mt = 0; mt < 4; mt++) {
#pragma unroll
                for (int np = 0; np < 4; np++) {
                    mma16816(acc[mt][np * 2],     af[mt], &bf[np][0]);
                    mma16816(acc[mt][np * 2 + 1], af[mt], &bf[np][2]);
                }
            }
        }
        __syncthreads();
        buf++; if (buf == NSTAGE) buf = 0;
    }
}

// Fused QKV projection: N-regions [0,2048)=Q fp32, [2048,2560)=K fp32,
// [2560,3072)=V fp16. Head-major outputs, bias from concat buffer.
__global__ __launch_bounds__(GEMM_THREADS) void tc_gemm_qkv_kernel(
    const __half* __restrict__ Ap, const __half* __restrict__ Bp,
    const float* __restrict__ bias,
    float* __restrict__ qout, float* __restrict__ kout,
    __half* __restrict__ vout)
{
    extern __shared__ char smem[];
    const uint32_t s_u32 = smem_to_u32(smem);
    const int t    = threadIdx.x;
    const int wid  = t >> 5;
    const int lane = t & 31;
    const int m0   = blockIdx.y * 128;
    const int n0   = blockIdx.x * 128;
    const int wm   = (wid >> 1) * 64;
    const int wn   = (wid & 1) * 64;

    float acc[4][8][4];
#pragma unroll
    for (int a = 0; a < 4; a++)
#pragma unroll
        for (int b = 0; b < 8; b++)
#pragma unroll
            for (int c = 0; c < 4; c++) acc[a][b][c] = 0.0f;

    gemm_mainloop(s_u32, Ap, Bp, m0, n0, HDIM, t, lane, wm, wn, acc);

    const int er = lane >> 2;
    const int ec = (lane & 3) * 2;
#pragma unroll
    for (int mt = 0; mt < 4; mt++) {
#pragma unroll
        for (int nt = 0; nt < 8; nt++) {
            int mloc = wm + mt * 16 + er;
            int nloc = wn + nt * 8 + ec;
            int m = m0 + mloc;
            int n = n0 + nloc;
            int bb = m >> 11, ss = m & 2047;
            float bx = bias[n], by = bias[n + 1];
            float v00 = acc[mt][nt][0] + bx, v01 = acc[mt][nt][1] + by;
            float v10 = acc[mt][nt][2] + bx, v11 = acc[mt][nt][3] + by;
            if (n0 < 2048) {               // Q region
                int head = n >> 7, d = n & 127;
                float* op = qout + (size_t)(((bb * NHQ + head) * S_LEN + ss) * HD + d);
                float2 a; a.x = v00; a.y = v01;
                float2 b; b.x = v10; b.y = v11;
                *(float2*)op = a;
                *(float2*)(op + 8 * HD) = b;
            } else if (n0 < 2560) {        // K region
                int nn = n - 2048;
                int head = nn >> 7, d = nn & 127;
                float* op = kout + (size_t)(((bb * NHKV + head) * S_LEN + ss) * HD + d);
                float2 a; a.x = v00; a.y = v01;
                float2 b; b.x = v10; b.y = v11;
                *(float2*)op = a;
                *(float2*)(op + 8 * HD) = b;
            } else {                       // V region -> fp16 direct
                int nn = n - 2560;
                int head = nn >> 7, d = nn & 127;
                __half* op = vout + (size_t)(((bb * NHKV + head) * S_LEN + ss) * HD + d);
                *(__half2*)op = __floats2half2_rn(v00, v01);
                *(__half2*)(op + 8 * HD) = __floats2half2_rn(v10, v11);
            }
        }
    }
}

// O-projection: row-major fp32, no bias.
__global__ __launch_bounds__(GEMM_THREADS) void tc_gemm_o_kernel(
    const __half* __restrict__ Ap, const __half* __restrict__ Bp,
    float* __restrict__ out)
{
    extern __shared__ char smem[];
    const uint32_t s_u32 = smem_to_u32(smem);
    const int t    = threadIdx.x;
    const int wid  = t >> 5;
    const int lane = t & 31;
    const int m0   = blockIdx.y * 128;
    const int n0   = blockIdx.x * 128;
    const int wm   = (wid >> 1) * 64;
    const int wn   = (wid & 1) * 64;

    float acc[4][8][4];
#pragma unroll
    for (int a = 0; a < 4; a++)
#pragma unroll
        for (int b = 0; b < 8; b++)
#pragma unroll
            for (int c = 0; c < 4; c++) acc[a][b][c] = 0.0f;

    gemm_mainloop(s_u32, Ap, Bp, m0, n0, HDIM, t, lane, wm, wn, acc);

    const int er = lane >> 2;
    const int ec = (lane & 3) * 2;
#pragma unroll
    for (int mt = 0; mt < 4; mt++) {
#pragma unroll
        for (int nt = 0; nt < 8; nt++) {
            int mloc = wm + mt * 16 + er;
            int nloc = wn + nt * 8 + ec;
            int m = m0 + mloc;
            float* op = out + (size_t)m * HDIM + n0 + nloc;
            float2 a; a.x = acc[mt][nt][0]; a.y = acc[mt][nt][1];
            float2 b; b.x = acc[mt][nt][2]; b.y = acc[mt][nt][3];
            *(float2*)op = a;
            *(float2*)(op + 8 * HDIM) = b;
        }
    }
}

// ---------------------------------------------------------------------------
// RoPE -> fp16 (scale folded in)
// ---------------------------------------------------------------------------
__global__ void rope16_kernel(const float* __restrict__ buf,
                              __half* __restrict__ out,
                              const int* __restrict__ pos_ids,
                              int NH, float scale)
{
    int idx = blockIdx.x * 256 + threadIdx.x;
    int total = BATCH * NH * S_LEN * 64;
    if (idx >= total) return;
    int i  = idx & 63;
    int s  = (idx >> 6) & 2047;
    int bh = idx >> 17;
    int b  = bh / NH;

    float p   = (float)pos_ids[b * S_LEN + s];
    float inv = expf(-(float)i * (13.815510557964274f / 64.0f));
    float ph  = p * inv;
    float c, sn;
    sincosf(ph, &sn, &c);

    size_t base = (size_t)(bh * S_LEN + s) * HD;
    float x1 = buf[base + i];
    float x2 = buf[base + 64 + i];
    out[base + i]      = __float2half_rn((x1 * c - x2 * sn) * scale);
    out[base + 64 + i] = __float2half_rn((x2 * c + x1 * sn) * scale);
}

// ---------------------------------------------------------------------------
// Tensor-core flash attention, fp16, causal, GQA.
// BM=128, BN=64, 8 warps. V natural layout + ldmatrix.trans for PV.
// K/V tiles double-buffered with cp.async. Heavy q-tiles scheduled FIRST
// (iq reversed vs blockIdx.x) to fix causal load-imbalance tail.
// ---------------------------------------------------------------------------
#define FQ_STR 136
#define FK_STR 136
#define SQ_OFF 0
#define KV_OFF (128 * FQ_STR)            // elems
#define KV_STAGE (2 * 64 * FK_STR)       // K tile + V tile per stage, elems
#define FLASH_SMEM_ELEMS (KV_OFF + 2 * KV_STAGE)
#define FLASH_SMEM_BYTES (FLASH_SMEM_ELEMS * 2)   // 104448 B

__device__ __forceinline__ void flash_load_kv(
    uint32_t s_u32, int stage_elems,
    const __half* __restrict__ Kp, const __half* __restrict__ Vp,
    int j, int t)
{
#pragma unroll
    for (int i = 0; i < 4; i++) {
        int chunk = t + i * 256;           // 0..1023
        int row = chunk >> 4;              // 0..63
        int cg  = chunk & 15;
        uint32_t kd = s_u32 + (stage_elems + row * FK_STR + cg * 8) * 2;
        uint32_t vd = kd + (64 * FK_STR) * 2;
        CP_ASYNC16(kd, Kp + (size_t)(j * 64 + row) * HD + cg * 8);
        CP_ASYNC16(vd, Vp + (size_t)(j * 64 + row) * HD + cg * 8);
    }
}

__global__ __launch_bounds__(256) void flash16_kernel(
    const __half* __restrict__ Qg, const __half* __restrict__ Kg,
    const __half* __restrict__ Vg, __half* __restrict__ Ag)
{
    extern __shared__ __align__(16) __half sb[];
    const uint32_t s_u32 = smem_to_u32(sb);

    // Heavy-first scheduling: largest iq gets the earliest block id.
    const int iq = (int)gridDim.x - 1 - (int)blockIdx.x;
    const int h  = blockIdx.y;
    const int b  = blockIdx.z;
    const int hkv = h >> 2;
    const int q0 = iq * 128;
    const int t    = threadIdx.x;
    const int wid  = t >> 5;
    const int lane = t & 31;

    const __half* Qp = Qg + (size_t)((b * NHQ + h) * S_LEN + q0) * HD;
    const __half* Kp = Kg + (size_t)((b * NHKV + hkv) * S_LEN) * HD;
    const __half* Vp = Vg + (size_t)((b * NHKV + hkv) * S_LEN) * HD;

    // Q tile via cp.async (group 0 together with KV tile 0)
#pragma unroll
    for (int i = 0; i < 8; i++) {
        int chunk = t + i * 256;
        int row = chunk >> 4;
        int cg  = chunk & 15;
        CP_ASYNC16(s_u32 + (SQ_OFF + row * FQ_STR + cg * 8) * 2,
                   Qp + (size_t)row * HD + cg * 8);
    }
    flash_load_kv(s_u32, KV_OFF, Kp, Vp, 0, t);
    CP_COMMIT();

    float o[16][4];
#pragma unroll
    for (int f = 0; f < 16; f++)
#pragma unroll
        for (int e = 0; e < 4; e++) o[f][e] = 0.0f;
    float m0 = -1e30f, m1 = -1e30f, l0 = 0.0f, l1 = 0.0f;

    const int a_row_l = lane & 15;
    const int a_col_l = (lane >> 4) * 8;
    const int b_row_l = ((lane >> 4) << 3) + (lane & 7);
    const int b_col_l = ((lane >> 3) & 1) * 8;
    const int er = lane >> 2;
    const int ec = (lane & 3) * 2;
    const int r0g = q0 + wid * 16 + er;
    const int r1g = r0g + 8;

    const int ntiles = (iq + 1) * 2;

    for (int j = 0; j < ntiles; j++) {
        int buf = j & 1;
        if (j + 1 < ntiles) {
            flash_load_kv(s_u32, KV_OFF + (buf ^ 1) * KV_STAGE, Kp, Vp, j + 1, t);
            CP_COMMIT();
            CP_WAIT(1);
        } else {
            CP_WAIT(0);
        }
        __syncthreads();

        const int skv = KV_OFF + buf * KV_STAGE;      // K tile base (elems)
        const int sv  = skv + 64 * FK_STR;            // V tile base

        // S = Q K^T
        float c[8][4];
#pragma unroll
        for (int nf = 0; nf < 8; nf++)
#pragma unroll
            for (int e = 0; e < 4; e++) c[nf][e] = 0.0f;

#pragma unroll
        for (int kh = 0; kh < 8; kh++) {
            uint32_t ah[4];
            uint32_t ad = s_u32 + (SQ_OFF + (wid * 16 + a_row_l) * FQ_STR +
                                   kh * 16 + a_col_l) * 2;
            ldsm_x4(ah, ad);
#pragma unroll
            for (int np = 0; np < 4; np++) {
                uint32_t bh[4];
                uint32_t bd = s_u32 + (skv + (np * 16 + b_row_l) * FK_STR +
                                       kh * 16 + b_col_l) * 2;
                ldsm_x4(bh, bd);
                mma16816(c[np * 2],     ah, &bh[0]);
                mma16816(c[np * 2 + 1], ah, &bh[2]);
            }
        }

        // Causal mask
        if (j >= 2 * iq) {
#pragma unroll
            for (int nf = 0; nf < 8; nf++) {
#pragma unroll
                for (int d = 0; d < 2; d++) {
                    int col = j * 64 + nf * 8 + ec + d;
                    if (col > r0g) c[nf][d]     = -1e30f;
                    if (col > r1g) c[nf][2 + d] = -1e30f;
                }
            }
        }

        // Online softmax
        float mx0 = -1e30f, mx1 = -1e30f;
#pragma unroll
        for (int nf = 0; nf < 8; nf++) {
            mx0 = fmaxf(mx0, fmaxf(c[nf][0], c[nf][1]));
            mx1 = fmaxf(mx1, fmaxf(c[nf][2], c[nf][3]));
        }
        mx0 = fmaxf(mx0, __shfl_xor_sync(0xffffffffu, mx0, 1));
        mx0 = fmaxf(mx0, __shfl_xor_sync(0xffffffffu, mx0, 2));
        mx1 = fmaxf(mx1, __shfl_xor_sync(0xffffffffu, mx1, 1));
        mx1 = fmaxf(mx1, __shfl_xor_sync(0xffffffffu, mx1, 2));

        float nm0 = fmaxf(m0, mx0), nm1 = fmaxf(m1, mx1);
        float al0 = __expf(m0 - nm0), al1 = __expf(m1 - nm1);
        m0 = nm0; m1 = nm1;

        float s0 = 0.0f, s1 = 0.0f;
#pragma unroll
        for (int nf = 0; nf < 8; nf++) {
            c[nf][0] = __expf(c[nf][0] - nm0);
            c[nf][1] = __expf(c[nf][1] - nm0);
            c[nf][2] = __expf(c[nf][2] - nm1);
            c[nf][3] = __expf(c[nf][3] - nm1);
            s0 += c[nf][0] + c[nf][1];
            s1 += c[nf][2] + c[nf][3];
        }
        s0 += __shfl_xor_sync(0xffffffffu, s0, 1);
        s0 += __shfl_xor_sync(0xffffffffu, s0, 2);
        s1 += __shfl_xor_sync(0xffffffffu, s1, 1);
        s1 += __shfl_xor_sync(0xffffffffu, s1, 2);
        l0 = l0 * al0 + s0;
        l1 = l1 * al1 + s1;

#pragma unroll
        for (int f = 0; f < 16; f++) {
            o[f][0] *= al0; o[f][1] *= al0;
            o[f][2] *= al1; o[f][3] *= al1;
        }

        // P @ V with trans-loaded B fragments from natural V layout
#pragma unroll
        for (int kf = 0; kf < 4; kf++) {
            int nf0 = kf * 2, nf1 = kf * 2 + 1;
            uint32_t pa[4];
            pa[0] = pack_h2(c[nf0][0], c[nf0][1]);
            pa[1] = pack_h2(c[nf0][2], c[nf0][3]);
            pa[2] = pack_h2(c[nf1][0], c[nf1][1]);
            pa[3] = pack_h2(c[nf1][2], c[nf1][3]);
#pragma unroll
            for (int nt = 0; nt < 8; nt++) {
                uint32_t bv[4];
                uint32_t bd = s_u32 + (sv + (kf * 16 + (lane & 15)) * FK_STR +
                                       nt * 16 + (lane >> 4) * 8) * 2;
                ldsm_x4_trans(bv, bd);
                mma16816(o[nt * 2],     pa, &bv[0]);
                mma16816(o[nt * 2 + 1], pa, &bv[2]);
            }
        }
        __syncthreads();
    }

    // Epilogue: fp16 row-major [m, h*128 + d]
    float inv0 = 1.0f / l0, inv1 = 1.0f / l1;
    __half* Ap0 = Ag + (size_t)(b * S_LEN + r0g) * HDIM + h * HD;
    __half* Ap1 = Ag + (size_t)(b * S_LEN + r1g) * HDIM + h * HD;
#pragma unroll
    for (int f = 0; f < 16; f++) {
        int col = (f >> 1) * 16 + (f & 1) * 8 + ec;
        __half2 v0 = __floats2half2_rn(o[f][0] * inv0, o[f][1] * inv0);
        __half2 v1 = __floats2half2_rn(o[f][2] * inv1, o[f][3] * inv1);
        *(__half2*)(Ap0 + col) = v0;
        *(__half2*)(Ap1 + col) = v1;
    }
}

// ---------------------------------------------------------------------------
// Launch
// ---------------------------------------------------------------------------
extern "C" void kernel_launch(void* const* d_in, const int* in_sizes, int n_in,
                              void* d_out, int out_size)
{
    const float* hs = (const float*)d_in[0];
    const float* wq = (const float*)d_in[1];
    const float* bq = (const float*)d_in[2];
    const float* wk = (const float*)d_in[3];
    const float* bk = (const float*)d_in[4];
    const float* wv = (const float*)d_in[5];
    const float* bv = (const float*)d_in[6];
    const float* wo = (const float*)d_in[7];
    const int*  pos = (const int*)d_in[8];
    float* out = (float*)d_out;

    float *qb, *kb, *bqkv;
    cudaGetSymbolAddress((void**)&qb, g_q);
    cudaGetSymbolAddress((void**)&kb, g_k);
    cudaGetSymbolAddress((void**)&bqkv, g_bqkv);

    __half *x16, *wqkv16, *wo16, *qh16, *kh16, *vh16, *a16;
    cudaGetSymbolAddress((void**)&x16,    g_x16);
    cudaGetSymbolAddress((void**)&wqkv16, g_wqkv16);
    cudaGetSymbolAddress((void**)&wo16,   g_wo16);
    cudaGetSymbolAddress((void**)&qh16,   g_qh16);
    cudaGetSymbolAddress((void**)&kh16,   g_kh16);
    cudaGetSymbolAddress((void**)&vh16,   g_vh16);
    cudaGetSymbolAddress((void**)&a16,    g_a16);

    cudaFuncSetAttribute(flash16_kernel,
                         cudaFuncAttributeMaxDynamicSharedMemorySize, FLASH_SMEM_BYTES);
    cudaFuncSetAttribute(tc_gemm_qkv_kernel,
                         cudaFuncAttributeMaxDynamicSharedMemorySize, GEMM_SMEM);
    cudaFuncSetAttribute(tc_gemm_o_kernel,
                         cudaFuncAttributeMaxDynamicSharedMemorySize, GEMM_SMEM);

    // 1. Single merged conversion launch + bias concat copies
    cvt_all_kernel<<<(CV_N4 + 255) / 256, 256>>>(
        hs, wq, wk, wv, wo, x16, wqkv16, wo16);
    cudaMemcpyAsync(bqkv,        bq, 2048 * 4, cudaMemcpyDeviceToDevice, 0);
    cudaMemcpyAsync(bqkv + 2048, bk,  512 * 4, cudaMemcpyDeviceToDevice, 0);
    cudaMemcpyAsync(bqkv + 2560, bv,  512 * 4, cudaMemcpyDeviceToDevice, 0);

    // 2. Fused QKV projection (768 CTAs, 128 threads each)
    tc_gemm_qkv_kernel<<<dim3(NQKV / 128, M_ROWS / 128), GEMM_THREADS, GEMM_SMEM>>>(
        x16, wqkv16, bqkv, qb, kb, vh16);

    // 3. RoPE -> fp16 (Q scaled by 1/sqrt(d))
    {
        int total_q = BATCH * NHQ * S_LEN * 64;
        int total_k = BATCH * NHKV * S_LEN * 64;
        rope16_kernel<<<(total_q + 255) / 256, 256>>>(
            qb, qh16, pos, NHQ, 0.08838834764831845f);
        rope16_kernel<<<(total_k + 255) / 256, 256>>>(
            kb, kh16, pos, NHKV, 1.0f);
    }

    // 4. Flash attention (fp16 MMA), heavy tiles first
    flash16_kernel<<<dim3(S_LEN / 128, NHQ, BATCH), 256, FLASH_SMEM_BYTES>>>(
        qh16, kh16, vh16, a16);

    // 5. O-projection -> d_out (row-major fp32)
    tc_gemm_o_kernel<<<dim3(HDIM / 128, M_ROWS / 128), GEMM_THREADS, GEMM_SMEM>>>(
        a16, wo16, out);
}

// round 14
// speedup vs baseline: 1.0422x; 1.0422x over previous
#include <cuda_runtime.h>
#include <cuda_fp16.h>
#include <math.h>
#include <cstdint>

// Problem constants
#define S_LEN 2048
#define HDIM  2048
#define NHQ   16
#define NHKV  4
#define HD    128
#define BATCH 2
#define M_ROWS (BATCH * S_LEN)   // 4096
#define NQKV  3072               // 2048 (Q) + 512 (K) + 512 (V)

// ---------------------------------------------------------------------------
// Scratch (allocation-free: __device__ globals)
// ---------------------------------------------------------------------------
__device__ float g_q[BATCH * NHQ * S_LEN * HD];     // fp32 pre-RoPE Q
__device__ float g_k[BATCH * NHKV * S_LEN * HD];

__device__ __half g_x16[M_ROWS * HDIM];             // hidden fp16
__device__ __half g_wqkv16[NQKV * HDIM];            // concat Wq|Wk|Wv fp16
__device__ __half g_wo16[HDIM * HDIM];
__device__ float  g_bqkv[NQKV];                     // concat bq|bk|bv
__device__ __half g_qh16[BATCH * NHQ * S_LEN * HD];   // post-RoPE Q (scaled)
__device__ __half g_kh16[BATCH * NHKV * S_LEN * HD];  // post-RoPE K
__device__ __half g_vh16[BATCH * NHKV * S_LEN * HD];  // V fp16 (direct)
__device__ __half g_a16[M_ROWS * HDIM];               // attn out, row-major

// ---------------------------------------------------------------------------
// PTX helpers
// ---------------------------------------------------------------------------
__device__ __forceinline__ uint32_t smem_to_u32(const void* smem_ptr) {
    uint32_t addr;
    asm("{ .reg .u64 tmp; cvta.to.shared.u64 tmp, %1; cvt.u32.u64 %0, tmp; }"
        : "=r"(addr) : "l"(smem_ptr));
    return addr;
}

__device__ __forceinline__ void ldsm_x4(uint32_t* r, uint32_t addr) {
    asm volatile("ldmatrix.sync.aligned.m8n8.x4.shared.b16 {%0,%1,%2,%3}, [%4];"
                 : "=r"(r[0]), "=r"(r[1]), "=r"(r[2]), "=r"(r[3]) : "r"(addr));
}

__device__ __forceinline__ void ldsm_x4_trans(uint32_t* r, uint32_t addr) {
    asm volatile("ldmatrix.sync.aligned.m8n8.x4.trans.shared.b16 {%0,%1,%2,%3}, [%4];"
                 : "=r"(r[0]), "=r"(r[1]), "=r"(r[2]), "=r"(r[3]) : "r"(addr));
}

__device__ __forceinline__ void mma16816(float* d, const uint32_t* a,
                                         const uint32_t* b) {
    asm volatile(
        "mma.sync.aligned.m16n8k16.row.col.f32.f16.f16.f32 "
        "{%0,%1,%2,%3}, {%4,%5,%6,%7}, {%8,%9}, {%0,%1,%2,%3};"
        : "+f"(d[0]), "+f"(d[1]), "+f"(d[2]), "+f"(d[3])
        : "r"(a[0]), "r"(a[1]), "r"(a[2]), "r"(a[3]), "r"(b[0]), "r"(b[1]));
}

#define CP_ASYNC16(dst_u32, src_ptr) \
    asm volatile("cp.async.cg.shared.global [%0], [%1], 16;" \
                 :: "r"(dst_u32), "l"(src_ptr))
#define CP_COMMIT() asm volatile("cp.async.commit_group;" ::: "memory")
#define CP_WAIT(n)  asm volatile("cp.async.wait_group %0;" :: "n"(n) : "memory")

__device__ __forceinline__ uint32_t pack_h2(float x, float y) {
    __half2 t = __floats2half2_rn(x, y);
    return *(uint32_t*)&t;
}

// ---------------------------------------------------------------------------
// fp32 -> fp16 convert
// ---------------------------------------------------------------------------
__global__ void cvt_h_kernel(const float* __restrict__ in,
                             __half* __restrict__ out, int n4)
{
    int i = blockIdx.x * 256 + threadIdx.x;
    if (i >= n4) return;
    float4 v = ((const float4*)in)[i];
    __half2 a = __floats2half2_rn(v.x, v.y);
    __half2 b = __floats2half2_rn(v.z, v.w);
    ((__half2*)out)[2 * i]     = a;
    ((__half2*)out)[2 * i + 1] = b;
}

// ---------------------------------------------------------------------------
// GEMM core: block 128x128, BK=32, 4 warps (2m x 2n), warp tile 64x64,
// 128 threads, 3-stage cp.async pipeline. MMA:ldsm ratio 4.0.  (R12-proven)
// ---------------------------------------------------------------------------
#define MATB (128 * 80)              // 10240 B per matrix tile
#define STAGEB (2 * MATB)            // A + B = 20480 B
#define NSTAGE 3
#define GEMM_SMEM (NSTAGE * STAGEB)  // 61440 B
#define GEMM_THREADS 128

__device__ __forceinline__ void gemm_copy_stage(
    uint32_t s_u32,
    const __half* __restrict__ Ap, const __half* __restrict__ Bp,
    int m0, int n0, int k0, int Kdim, int t)
{
#pragma unroll
    for (int i = 0; i < 4; i++) {
        int chunk = t + i * GEMM_THREADS;      // 0..511
        int row = chunk >> 2;
        int ch  = chunk & 3;
        uint32_t dst = s_u32 + row * 80 + ch * 16;
        size_t aoff = (size_t)(m0 + row) * Kdim + k0 + ch * 8;
        size_t boff = (size_t)(n0 + row) * Kdim + k0 + ch * 8;
        CP_ASYNC16(dst,        Ap + aoff);
        CP_ASYNC16(dst + MATB, Bp + boff);
    }
}

// Mainloop: fills acc[4][8][4] (warp tile 64x64).
__device__ __forceinline__ void gemm_mainloop(
    uint32_t s_u32, const __half* Ap, const __half* Bp,
    int m0, int n0, int Kdim, int t, int lane,
    int wm, int wn, float acc[4][8][4])
{
    const int nsteps = Kdim >> 5;
    const int a_row_l = lane & 15;
    const int a_col_l = (lane >> 4) * 8;
    const int b_row_l = ((lane >> 4) << 3) + (lane & 7);
    const int b_col_l = ((lane >> 3) & 1) * 8;

    // Prologue: stages 0, 1
    gemm_copy_stage(s_u32,          Ap, Bp, m0, n0, 0,  Kdim, t);
    CP_COMMIT();
    gemm_copy_stage(s_u32 + STAGEB, Ap, Bp, m0, n0, 32, Kdim, t);
    CP_COMMIT();

    int buf = 0;
    for (int s = 0; s < nsteps; s++) {
        if (s + 1 < nsteps) { CP_WAIT(1); } else { CP_WAIT(0); }
        __syncthreads();

        if (s + 2 < nsteps) {
            int nb = buf + 2; if (nb >= NSTAGE) nb -= NSTAGE;
            gemm_copy_stage(s_u32 + nb * STAGEB, Ap, Bp,
                            m0, n0, (s + 2) << 5, Kdim, t);
            CP_COMMIT();
        }

        uint32_t sA = s_u32 + buf * STAGEB;
        uint32_t sB = sA + MATB;

#pragma unroll
        for (int kh = 0; kh < 2; kh++) {
            uint32_t af[4][4], bf[4][4];
#pragma unroll
            for (int mt = 0; mt < 4; mt++) {
                uint32_t ad = sA + (wm + mt * 16 + a_row_l) * 80 +
                              (kh * 16 + a_col_l) * 2;
                ldsm_x4(af[mt], ad);
            }
#pragma unroll
            for (int np = 0; np < 4; np++) {
                uint32_t bd = sB + (wn + np * 16 + b_row_l) * 80 +
                              (kh * 16 + b_col_l) * 2;
                ldsm_x4(bf[np], bd);
            }
#pragma unroll
            for (int mt = 0; mt < 4; mt++) {
#pragma unroll
                for (int np = 0; np < 4; np++) {
                    mma16816(acc[mt][np * 2],     af[mt], &bf[np][0]);
                    mma16816(acc[mt][np * 2 + 1], af[mt], &bf[np][2]);
                }
            }
        }
        __syncthreads();
        buf++; if (buf == NSTAGE) buf = 0;
    }
}

// Fused QKV projection: N-regions [0,2048)=Q fp32, [2048,2560)=K fp32,
// [2560,3072)=V fp16. Head-major outputs, bias from concat buffer.
__global__ __launch_bounds__(GEMM_THREADS) void tc_gemm_qkv_kernel(
    const __half* __restrict__ Ap, const __half* __restrict__ Bp,
    const float* __restrict__ bias,
    float* __restrict__ qout, float* __restrict__ kout,
    __half* __restrict__ vout)
{
    extern __shared__ char smem[];
    const uint32_t s_u32 = smem_to_u32(smem);
    const int t    = threadIdx.x;
    const int wid  = t >> 5;
    const int lane = t & 31;
    const int m0   = blockIdx.y * 128;
    const int n0   = blockIdx.x * 128;
    const int wm   = (wid >> 1) * 64;
    const int wn   = (wid & 1) * 64;

    float acc[4][8][4];
#pragma unroll
    for (int a = 0; a < 4; a++)
#pragma unroll
        for (int b = 0; b < 8; b++)
#pragma unroll
            for (int c = 0; c < 4; c++) acc[a][b][c] = 0.0f;

    gemm_mainloop(s_u32, Ap, Bp, m0, n0, HDIM, t, lane, wm, wn, acc);

    const int er = lane >> 2;
    const int ec = (lane & 3) * 2;
#pragma unroll
    for (int mt = 0; mt < 4; mt++) {
#pragma unroll
        for (int nt = 0; nt < 8; nt++) {
            int mloc = wm + mt * 16 + er;
            int nloc = wn + nt * 8 + ec;
            int m = m0 + mloc;
            int n = n0 + nloc;
            int bb = m >> 11, ss = m & 2047;
            float bx = bias[n], by = bias[n + 1];
            float v00 = acc[mt][nt][0] + bx, v01 = acc[mt][nt][1] + by;
            float v10 = acc[mt][nt][2] + bx, v11 = acc[mt][nt][3] + by;
            if (n0 < 2048) {               // Q region
                int head = n >> 7, d = n & 127;
                float* op = qout + (size_t)(((bb * NHQ + head) * S_LEN + ss) * HD + d);
                float2 a; a.x = v00; a.y = v01;
                float2 b; b.x = v10; b.y = v11;
                *(float2*)op = a;
                *(float2*)(op + 8 * HD) = b;
            } else if (n0 < 2560) {        // K region
                int nn = n - 2048;
                int head = nn >> 7, d = nn & 127;
                float* op = kout + (size_t)(((bb * NHKV + head) * S_LEN + ss) * HD + d);
                float2 a; a.x = v00; a.y = v01;
                float2 b; b.x = v10; b.y = v11;
                *(float2*)op = a;
                *(float2*)(op + 8 * HD) = b;
            } else {                       // V region -> fp16 direct
                int nn = n - 2560;
                int head = nn >> 7, d = nn & 127;
                __half* op = vout + (size_t)(((bb * NHKV + head) * S_LEN + ss) * HD + d);
                *(__half2*)op = __floats2half2_rn(v00, v01);
                *(__half2*)(op + 8 * HD) = __floats2half2_rn(v10, v11);
            }
        }
    }
}

// O-projection: row-major fp32, no bias.
__global__ __launch_bounds__(GEMM_THREADS) void tc_gemm_o_kernel(
    const __half* __restrict__ Ap, const __half* __restrict__ Bp,
    float* __restrict__ out)
{
    extern __shared__ char smem[];
    const uint32_t s_u32 = smem_to_u32(smem);
    const int t    = threadIdx.x;
    const int wid  = t >> 5;
    const int lane = t & 31;
    const int m0   = blockIdx.y * 128;
    const int n0   = blockIdx.x * 128;
    const int wm   = (wid >> 1) * 64;
    const int wn   = (wid & 1) * 64;

    float acc[4][8][4];
#pragma unroll
    for (int a = 0; a < 4; a++)
#pragma unroll
        for (int b = 0; b < 8; b++)
#pragma unroll
            for (int c = 0; c < 4; c++) acc[a][b][c] = 0.0f;

    gemm_mainloop(s_u32, Ap, Bp, m0, n0, HDIM, t, lane, wm, wn, acc);

    const int er = lane >> 2;
    const int ec = (lane & 3) * 2;
#pragma unroll
    for (int mt = 0; mt < 4; mt++) {
#pragma unroll
        for (int nt = 0; nt < 8; nt++) {
            int mloc = wm + mt * 16 + er;
            int nloc = wn + nt * 8 + ec;
            int m = m0 + mloc;
            float* op = out + (size_t)m * HDIM + n0 + nloc;
            float2 a; a.x = acc[mt][nt][0]; a.y = acc[mt][nt][1];
            float2 b; b.x = acc[mt][nt][2]; b.y = acc[mt][nt][3];
            *(float2*)op = a;
            *(float2*)(op + 8 * HDIM) = b;
        }
    }
}

// ---------------------------------------------------------------------------
// RoPE -> fp16 (scale folded in)
// ---------------------------------------------------------------------------
__global__ void rope16_kernel(const float* __restrict__ buf,
                              __half* __restrict__ out,
                              const int* __restrict__ pos_ids,
                              int NH, float scale)
{
    int idx = blockIdx.x * 256 + threadIdx.x;
    int total = BATCH * NH * S_LEN * 64;
    if (idx >= total) return;
    int i  = idx & 63;
    int s  = (idx >> 6) & 2047;
    int bh = idx >> 17;
    int b  = bh / NH;

    float p   = (float)pos_ids[b * S_LEN + s];
    float inv = expf(-(float)i * (13.815510557964274f / 64.0f));
    float ph  = p * inv;
    float c, sn;
    sincosf(ph, &sn, &c);

    size_t base = (size_t)(bh * S_LEN + s) * HD;
    float x1 = buf[base + i];
    float x2 = buf[base + 64 + i];
    out[base + i]      = __float2half_rn((x1 * c - x2 * sn) * scale);
    out[base + 64 + i] = __float2half_rn((x2 * c + x1 * sn) * scale);
}

// ---------------------------------------------------------------------------
// Tensor-core flash attention, fp16, causal, GQA.
// BM=128, BN=64, 8 warps. V natural layout + ldmatrix.trans for PV.
// K/V tiles double-buffered with cp.async. ONLY change vs R12: heavy q-tiles
// scheduled FIRST (iq reversed vs blockIdx.x) to fix causal tail imbalance.
// ---------------------------------------------------------------------------
#define FQ_STR 136
#define FK_STR 136
#define SQ_OFF 0
#define KV_OFF (128 * FQ_STR)            // elems
#define KV_STAGE (2 * 64 * FK_STR)       // K tile + V tile per stage, elems
#define FLASH_SMEM_ELEMS (KV_OFF + 2 * KV_STAGE)
#define FLASH_SMEM_BYTES (FLASH_SMEM_ELEMS * 2)   // 104448 B

__device__ __forceinline__ void flash_load_kv(
    uint32_t s_u32, int stage_elems,
    const __half* __restrict__ Kp, const __half* __restrict__ Vp,
    int j, int t)
{
#pragma unroll
    for (int i = 0; i < 4; i++) {
        int chunk = t + i * 256;           // 0..1023
        int row = chunk >> 4;              // 0..63
        int cg  = chunk & 15;
        uint32_t kd = s_u32 + (stage_elems + row * FK_STR + cg * 8) * 2;
        uint32_t vd = kd + (64 * FK_STR) * 2;
        CP_ASYNC16(kd, Kp + (size_t)(j * 64 + row) * HD + cg * 8);
        CP_ASYNC16(vd, Vp + (size_t)(j * 64 + row) * HD + cg * 8);
    }
}

__global__ __launch_bounds__(256) void flash16_kernel(
    const __half* __restrict__ Qg, const __half* __restrict__ Kg,
    const __half* __restrict__ Vg, __half* __restrict__ Ag)
{
    extern __shared__ __align__(16) __half sb[];
    const uint32_t s_u32 = smem_to_u32(sb);

    // Heavy-first scheduling: largest iq gets the earliest block id.
    const int iq = (int)gridDim.x - 1 - (int)blockIdx.x;
    const int h  = blockIdx.y;
    const int b  = blockIdx.z;
    const int hkv = h >> 2;
    const int q0 = iq * 128;
    const int t    = threadIdx.x;
    const int wid  = t >> 5;
    const int lane = t & 31;

    const __half* Qp = Qg + (size_t)((b * NHQ + h) * S_LEN + q0) * HD;
    const __half* Kp = Kg + (size_t)((b * NHKV + hkv) * S_LEN) * HD;
    const __half* Vp = Vg + (size_t)((b * NHKV + hkv) * S_LEN) * HD;

    // Q tile via cp.async (group 0 together with KV tile 0)
#pragma unroll
    for (int i = 0; i < 8; i++) {
        int chunk = t + i * 256;
        int row = chunk >> 4;
        int cg  = chunk & 15;
        CP_ASYNC16(s_u32 + (SQ_OFF + row * FQ_STR + cg * 8) * 2,
                   Qp + (size_t)row * HD + cg * 8);
    }
    flash_load_kv(s_u32, KV_OFF, Kp, Vp, 0, t);
    CP_COMMIT();

    float o[16][4];
#pragma unroll
    for (int f = 0; f < 16; f++)
#pragma unroll
        for (int e = 0; e < 4; e++) o[f][e] = 0.0f;
    float m0 = -1e30f, m1 = -1e30f, l0 = 0.0f, l1 = 0.0f;

    const int a_row_l = lane & 15;
    const int a_col_l = (lane >> 4) * 8;
    const int b_row_l = ((lane >> 4) << 3) + (lane & 7);
    const int b_col_l = ((lane >> 3) & 1) * 8;
    const int er = lane >> 2;
    const int ec = (lane & 3) * 2;
    const int r0g = q0 + wid * 16 + er;
    const int r1g = r0g + 8;

    const int ntiles = (iq + 1) * 2;

    for (int j = 0; j < ntiles; j++) {
        int buf = j & 1;
        if (j + 1 < ntiles) {
            flash_load_kv(s_u32, KV_OFF + (buf ^ 1) * KV_STAGE, Kp, Vp, j + 1, t);
            CP_COMMIT();
            CP_WAIT(1);
        } else {
            CP_WAIT(0);
        }
        __syncthreads();

        const int skv = KV_OFF + buf * KV_STAGE;      // K tile base (elems)
        const int sv  = skv + 64 * FK_STR;            // V tile base

        // S = Q K^T
        float c[8][4];
#pragma unroll
        for (int nf = 0; nf < 8; nf++)
#pragma unroll
            for (int e = 0; e < 4; e++) c[nf][e] = 0.0f;

#pragma unroll
        for (int kh = 0; kh < 8; kh++) {
            uint32_t ah[4];
            uint32_t ad = s_u32 + (SQ_OFF + (wid * 16 + a_row_l) * FQ_STR +
                                   kh * 16 + a_col_l) * 2;
            ldsm_x4(ah, ad);
#pragma unroll
            for (int np = 0; np < 4; np++) {
                uint32_t bh[4];
                uint32_t bd = s_u32 + (skv + (np * 16 + b_row_l) * FK_STR +
                                       kh * 16 + b_col_l) * 2;
                ldsm_x4(bh, bd);
                mma16816(c[np * 2],     ah, &bh[0]);
                mma16816(c[np * 2 + 1], ah, &bh[2]);
            }
        }

        // Causal mask
        if (j >= 2 * iq) {
#pragma unroll
            for (int nf = 0; nf < 8; nf++) {
#pragma unroll
                for (int d = 0; d < 2; d++) {
                    int col = j * 64 + nf * 8 + ec + d;
                    if (col > r0g) c[nf][d]     = -1e30f;
                    if (col > r1g) c[nf][2 + d] = -1e30f;
                }
            }
        }

        // Online softmax
        float mx0 = -1e30f, mx1 = -1e30f;
#pragma unroll
        for (int nf = 0; nf < 8; nf++) {
            mx0 = fmaxf(mx0, fmaxf(c[nf][0], c[nf][1]));
            mx1 = fmaxf(mx1, fmaxf(c[nf][2], c[nf][3]));
        }
        mx0 = fmaxf(mx0, __shfl_xor_sync(0xffffffffu, mx0, 1));
        mx0 = fmaxf(mx0, __shfl_xor_sync(0xffffffffu, mx0, 2));
        mx1 = fmaxf(mx1, __shfl_xor_sync(0xffffffffu, mx1, 1));
        mx1 = fmaxf(mx1, __shfl_xor_sync(0xffffffffu, mx1, 2));

        float nm0 = fmaxf(m0, mx0), nm1 = fmaxf(m1, mx1);
        float al0 = __expf(m0 - nm0), al1 = __expf(m1 - nm1);
        m0 = nm0; m1 = nm1;

        float s0 = 0.0f, s1 = 0.0f;
#pragma unroll
        for (int nf = 0; nf < 8; nf++) {
            c[nf][0] = __expf(c[nf][0] - nm0);
            c[nf][1] = __expf(c[nf][1] - nm0);
            c[nf][2] = __expf(c[nf][2] - nm1);
            c[nf][3] = __expf(c[nf][3] - nm1);
            s0 += c[nf][0] + c[nf][1];
            s1 += c[nf][2] + c[nf][3];
        }
        s0 += __shfl_xor_sync(0xffffffffu, s0, 1);
        s0 += __shfl_xor_sync(0xffffffffu, s0, 2);
        s1 += __shfl_xor_sync(0xffffffffu, s1, 1);
        s1 += __shfl_xor_sync(0xffffffffu, s1, 2);
        l0 = l0 * al0 + s0;
        l1 = l1 * al1 + s1;

#pragma unroll
        for (int f = 0; f < 16; f++) {
            o[f][0] *= al0; o[f][1] *= al0;
            o[f][2] *= al1; o[f][3] *= al1;
        }

        // P @ V with trans-loaded B fragments from natural V layout
#pragma unroll
        for (int kf = 0; kf < 4; kf++) {
            int nf0 = kf * 2, nf1 = kf * 2 + 1;
            uint32_t pa[4];
            pa[0] = pack_h2(c[nf0][0], c[nf0][1]);
            pa[1] = pack_h2(c[nf0][2], c[nf0][3]);
            pa[2] = pack_h2(c[nf1][0], c[nf1][1]);
            pa[3] = pack_h2(c[nf1][2], c[nf1][3]);
#pragma unroll
            for (int nt = 0; nt < 8; nt++) {
                uint32_t bv[4];
                uint32_t bd = s_u32 + (sv + (kf * 16 + (lane & 15)) * FK_STR +
                                       nt * 16 + (lane >> 4) * 8) * 2;
                ldsm_x4_trans(bv, bd);
                mma16816(o[nt * 2],     pa, &bv[0]);
                mma16816(o[nt * 2 + 1], pa, &bv[2]);
            }
        }
        __syncthreads();
    }

    // Epilogue: fp16 row-major [m, h*128 + d]
    float inv0 = 1.0f / l0, inv1 = 1.0f / l1;
    __half* Ap0 = Ag + (size_t)(b * S_LEN + r0g) * HDIM + h * HD;
    __half* Ap1 = Ag + (size_t)(b * S_LEN + r1g) * HDIM + h * HD;
#pragma unroll
    for (int f = 0; f < 16; f++) {
        int col = (f >> 1) * 16 + (f & 1) * 8 + ec;
        __half2 v0 = __floats2half2_rn(o[f][0] * inv0, o[f][1] * inv0);
        __half2 v1 = __floats2half2_rn(o[f][2] * inv1, o[f][3] * inv1);
        *(__half2*)(Ap0 + col) = v0;
        *(__half2*)(Ap1 + col) = v1;
    }
}

// ---------------------------------------------------------------------------
// Launch
// ---------------------------------------------------------------------------
extern "C" void kernel_launch(void* const* d_in, const int* in_sizes, int n_in,
                              void* d_out, int out_size)
{
    const float* hs = (const float*)d_in[0];
    const float* wq = (const float*)d_in[1];
    const float* bq = (const float*)d_in[2];
    const float* wk = (const float*)d_in[3];
    const float* bk = (const float*)d_in[4];
    const float* wv = (const float*)d_in[5];
    const float* bv = (const float*)d_in[6];
    const float* wo = (const float*)d_in[7];
    const int*  pos = (const int*)d_in[8];
    float* out = (float*)d_out;

    float *qb, *kb, *bqkv;
    cudaGetSymbolAddress((void**)&qb, g_q);
    cudaGetSymbolAddress((void**)&kb, g_k);
    cudaGetSymbolAddress((void**)&bqkv, g_bqkv);

    __half *x16, *wqkv16, *wo16, *qh16, *kh16, *vh16, *a16;
    cudaGetSymbolAddress((void**)&x16,    g_x16);
    cudaGetSymbolAddress((void**)&wqkv16, g_wqkv16);
    cudaGetSymbolAddress((void**)&wo16,   g_wo16);
    cudaGetSymbolAddress((void**)&qh16,   g_qh16);
    cudaGetSymbolAddress((void**)&kh16,   g_kh16);
    cudaGetSymbolAddress((void**)&vh16,   g_vh16);
    cudaGetSymbolAddress((void**)&a16,    g_a16);

    cudaFuncSetAttribute(flash16_kernel,
                         cudaFuncAttributeMaxDynamicSharedMemorySize, FLASH_SMEM_BYTES);
    cudaFuncSetAttribute(tc_gemm_qkv_kernel,
                         cudaFuncAttributeMaxDynamicSharedMemorySize, GEMM_SMEM);
    cudaFuncSetAttribute(tc_gemm_o_kernel,
                         cudaFuncAttributeMaxDynamicSharedMemorySize, GEMM_SMEM);

    // 1. Convert inputs to fp16 (weights into concat buffer) + concat biases
    {
        int n4x = (M_ROWS * HDIM) / 4;
        cvt_h_kernel<<<(n4x + 255) / 256, 256>>>(hs, x16, n4x);
        int n4q = (HDIM * HDIM) / 4;
        cvt_h_kernel<<<(n4q + 255) / 256, 256>>>(wq, wqkv16, n4q);
        int n4k = (NHKV * HD * HDIM) / 4;
        cvt_h_kernel<<<(n4k + 255) / 256, 256>>>(wk, wqkv16 + 2048 * HDIM, n4k);
        cvt_h_kernel<<<(n4k + 255) / 256, 256>>>(wv, wqkv16 + 2560 * HDIM, n4k);
        cvt_h_kernel<<<(n4q + 255) / 256, 256>>>(wo, wo16, n4q);
        cudaMemcpyAsync(bqkv,        bq, 2048 * 4, cudaMemcpyDeviceToDevice, 0);
        cudaMemcpyAsync(bqkv + 2048, bk,  512 * 4, cudaMemcpyDeviceToDevice, 0);
        cudaMemcpyAsync(bqkv + 2560, bv,  512 * 4, cudaMemcpyDeviceToDevice, 0);
    }

    // 2. Fused QKV projection (768 CTAs, 128 threads each)
    tc_gemm_qkv_kernel<<<dim3(NQKV / 128, M_ROWS / 128), GEMM_THREADS, GEMM_SMEM>>>(
        x16, wqkv16, bqkv, qb, kb, vh16);

    // 3. RoPE -> fp16 (Q scaled by 1/sqrt(d))
    {
        int total_q = BATCH * NHQ * S_LEN * 64;
        int total_k = BATCH * NHKV * S_LEN * 64;
        rope16_kernel<<<(total_q + 255) / 256, 256>>>(
            qb, qh16, pos, NHQ, 0.08838834764831845f);
        rope16_kernel<<<(total_k + 255) / 256, 256>>>(
            kb, kh16, pos, NHKV, 1.0f);
    }

    // 4. Flash attention (fp16 MMA), heavy tiles first
    flash16_kernel<<<dim3(S_LEN / 128, NHQ, BATCH), 256, FLASH_SMEM_BYTES>>>(
        qh16, kh16, vh16, a16);

    // 5. O-projection -> d_out (row-major fp32)
    tc_gemm_o_kernel<<<dim3(HDIM / 128, M_ROWS / 128), GEMM_THREADS, GEMM_SMEM>>>(
        a16, wo16, out);
}

// round 15
// speedup vs baseline: 1.0559x; 1.0132x over previous
#include <cuda_runtime.h>
#include <cuda_fp16.h>
#include <math.h>
#include <cstdint>

// Problem constants
#define S_LEN 2048
#define HDIM  2048
#define NHQ   16
#define NHKV  4
#define HD    128
#define BATCH 2
#define M_ROWS (BATCH * S_LEN)   // 4096
#define NQKV  3072               // 2048 (Q) + 512 (K) + 512 (V)

// ---------------------------------------------------------------------------
// Scratch (allocation-free: __device__ globals)
// ---------------------------------------------------------------------------
__device__ __half g_x16[M_ROWS * HDIM];             // hidden fp16
__device__ __half g_wqkv16[NQKV * HDIM];            // concat Wq|Wk|Wv fp16
__device__ __half g_wo16[HDIM * HDIM];
__device__ float  g_bqkv[NQKV];                     // concat bq|bk|bv
__device__ __half g_qh16[BATCH * NHQ * S_LEN * HD];   // post-RoPE Q (scaled)
__device__ __half g_kh16[BATCH * NHKV * S_LEN * HD];  // post-RoPE K
__device__ __half g_vh16[BATCH * NHKV * S_LEN * HD];  // V fp16 (direct)
__device__ __half g_a16[M_ROWS * HDIM];               // attn out, row-major

// ---------------------------------------------------------------------------
// PTX helpers
// ---------------------------------------------------------------------------
__device__ __forceinline__ uint32_t smem_to_u32(const void* smem_ptr) {
    uint32_t addr;
    asm("{ .reg .u64 tmp; cvta.to.shared.u64 tmp, %1; cvt.u32.u64 %0, tmp; }"
        : "=r"(addr) : "l"(smem_ptr));
    return addr;
}

__device__ __forceinline__ void ldsm_x4(uint32_t* r, uint32_t addr) {
    asm volatile("ldmatrix.sync.aligned.m8n8.x4.shared.b16 {%0,%1,%2,%3}, [%4];"
                 : "=r"(r[0]), "=r"(r[1]), "=r"(r[2]), "=r"(r[3]) : "r"(addr));
}

__device__ __forceinline__ void ldsm_x4_trans(uint32_t* r, uint32_t addr) {
    asm volatile("ldmatrix.sync.aligned.m8n8.x4.trans.shared.b16 {%0,%1,%2,%3}, [%4];"
                 : "=r"(r[0]), "=r"(r[1]), "=r"(r[2]), "=r"(r[3]) : "r"(addr));
}

__device__ __forceinline__ void mma16816(float* d, const uint32_t* a,
                                         const uint32_t* b) {
    asm volatile(
        "mma.sync.aligned.m16n8k16.row.col.f32.f16.f16.f32 "
        "{%0,%1,%2,%3}, {%4,%5,%6,%7}, {%8,%9}, {%0,%1,%2,%3};"
        : "+f"(d[0]), "+f"(d[1]), "+f"(d[2]), "+f"(d[3])
        : "r"(a[0]), "r"(a[1]), "r"(a[2]), "r"(a[3]), "r"(b[0]), "r"(b[1]));
}

#define CP_ASYNC16(dst_u32, src_ptr) \
    asm volatile("cp.async.cg.shared.global [%0], [%1], 16;" \
                 :: "r"(dst_u32), "l"(src_ptr))
#define CP_COMMIT() asm volatile("cp.async.commit_group;" ::: "memory")
#define CP_WAIT(n)  asm volatile("cp.async.wait_group %0;" :: "n"(n) : "memory")

__device__ __forceinline__ uint32_t pack_h2(float x, float y) {
    __half2 t = __floats2half2_rn(x, y);
    return *(uint32_t*)&t;
}

// ---------------------------------------------------------------------------
// fp32 -> fp16 convert
// ---------------------------------------------------------------------------
__global__ void cvt_h_kernel(const float* __restrict__ in,
                             __half* __restrict__ out, int n4)
{
    int i = blockIdx.x * 256 + threadIdx.x;
    if (i >= n4) return;
    float4 v = ((const float4*)in)[i];
    __half2 a = __floats2half2_rn(v.x, v.y);
    __half2 b = __floats2half2_rn(v.z, v.w);
    ((__half2*)out)[2 * i]     = a;
    ((__half2*)out)[2 * i + 1] = b;
}

// ---------------------------------------------------------------------------
// GEMM core: block 128x128, BK=32, 4 warps (2m x 2n), warp tile 64x64,
// 128 threads, 3-stage cp.async pipeline. MMA:ldsm ratio 4.0.  (R12-proven)
// ---------------------------------------------------------------------------
#define MATB (128 * 80)              // 10240 B per matrix tile
#define STAGEB (2 * MATB)            // A + B = 20480 B
#define NSTAGE 3
#define EPI_STR 132                  // fp32 epilogue smem row stride (floats)
#define EPI_BYTES (128 * EPI_STR * 4)             // 67584
#define GEMM_SMEM (EPI_BYTES)        // >= NSTAGE*STAGEB (61440); epilogue reuse
#define GEMM_THREADS 128

__device__ __forceinline__ void gemm_copy_stage(
    uint32_t s_u32,
    const __half* __restrict__ Ap, const __half* __restrict__ Bp,
    int m0, int n0, int k0, int Kdim, int t)
{
#pragma unroll
    for (int i = 0; i < 4; i++) {
        int chunk = t + i * GEMM_THREADS;      // 0..511
        int row = chunk >> 2;
        int ch  = chunk & 3;
        uint32_t dst = s_u32 + row * 80 + ch * 16;
        size_t aoff = (size_t)(m0 + row) * Kdim + k0 + ch * 8;
        size_t boff = (size_t)(n0 + row) * Kdim + k0 + ch * 8;
        CP_ASYNC16(dst,        Ap + aoff);
        CP_ASYNC16(dst + MATB, Bp + boff);
    }
}

// Mainloop: fills acc[4][8][4] (warp tile 64x64).
__device__ __forceinline__ void gemm_mainloop(
    uint32_t s_u32, const __half* Ap, const __half* Bp,
    int m0, int n0, int Kdim, int t, int lane,
    int wm, int wn, float acc[4][8][4])
{
    const int nsteps = Kdim >> 5;
    const int a_row_l = lane & 15;
    const int a_col_l = (lane >> 4) * 8;
    const int b_row_l = ((lane >> 4) << 3) + (lane & 7);
    const int b_col_l = ((lane >> 3) & 1) * 8;

    // Prologue: stages 0, 1
    gemm_copy_stage(s_u32,          Ap, Bp, m0, n0, 0,  Kdim, t);
    CP_COMMIT();
    gemm_copy_stage(s_u32 + STAGEB, Ap, Bp, m0, n0, 32, Kdim, t);
    CP_COMMIT();

    int buf = 0;
    for (int s = 0; s < nsteps; s++) {
        if (s + 1 < nsteps) { CP_WAIT(1); } else { CP_WAIT(0); }
        __syncthreads();

        if (s + 2 < nsteps) {
            int nb = buf + 2; if (nb >= NSTAGE) nb -= NSTAGE;
            gemm_copy_stage(s_u32 + nb * STAGEB, Ap, Bp,
                            m0, n0, (s + 2) << 5, Kdim, t);
            CP_COMMIT();
        }

        uint32_t sA = s_u32 + buf * STAGEB;
        uint32_t sB = sA + MATB;

#pragma unroll
        for (int kh = 0; kh < 2; kh++) {
            uint32_t af[4][4], bf[4][4];
#pragma unroll
            for (int mt = 0; mt < 4; mt++) {
                uint32_t ad = sA + (wm + mt * 16 + a_row_l) * 80 +
                              (kh * 16 + a_col_l) * 2;
                ldsm_x4(af[mt], ad);
            }
#pragma unroll
            for (int np = 0; np < 4; np++) {
                uint32_t bd = sB + (wn + np * 16 + b_row_l) * 80 +
                              (kh * 16 + b_col_l) * 2;
                ldsm_x4(bf[np], bd);
            }
#pragma unroll
            for (int mt = 0; mt < 4; mt++) {
#pragma unroll
                for (int np = 0; np < 4; np++) {
                    mma16816(acc[mt][np * 2],     af[mt], &bf[np][0]);
                    mma16816(acc[mt][np * 2 + 1], af[mt], &bf[np][2]);
                }
            }
        }
        __syncthreads();
        buf++; if (buf == NSTAGE) buf = 0;
    }
}

// Fused QKV projection + RoPE.
// N-regions: [0,2048)=Q (rope, scale, fp16), [2048,2560)=K (rope, fp16),
// [2560,3072)=V (fp16 direct). Each 128-col block = one head.
__global__ __launch_bounds__(GEMM_THREADS) void tc_gemm_qkv_kernel(
    const __half* __restrict__ Ap, const __half* __restrict__ Bp,
    const float* __restrict__ bias, const int* __restrict__ pos_ids,
    __half* __restrict__ qout, __half* __restrict__ kout,
    __half* __restrict__ vout)
{
    extern __shared__ char smem[];
    const uint32_t s_u32 = smem_to_u32(smem);
    float* smf = (float*)smem;
    const int t    = threadIdx.x;
    const int wid  = t >> 5;
    const int lane = t & 31;
    const int m0   = blockIdx.y * 128;
    const int n0   = blockIdx.x * 128;
    const int wm   = (wid >> 1) * 64;
    const int wn   = (wid & 1) * 64;

    float acc[4][8][4];
#pragma unroll
    for (int a = 0; a < 4; a++)
#pragma unroll
        for (int b = 0; b < 8; b++)
#pragma unroll
            for (int c = 0; c < 4; c++) acc[a][b][c] = 0.0f;

    gemm_mainloop(s_u32, Ap, Bp, m0, n0, HDIM, t, lane, wm, wn, acc);

    const int er = lane >> 2;
    const int ec = (lane & 3) * 2;

    if (n0 >= 2560) {
        // V region -> fp16 head-major direct (unchanged path)
#pragma unroll
        for (int mt = 0; mt < 4; mt++) {
#pragma unroll
            for (int nt = 0; nt < 8; nt++) {
                int mloc = wm + mt * 16 + er;
                int nloc = wn + nt * 8 + ec;
                int m = m0 + mloc;
                int n = n0 + nloc;
                int bb = m >> 11, ss = m & 2047;
                float bx = bias[n], by = bias[n + 1];
                float v00 = acc[mt][nt][0] + bx, v01 = acc[mt][nt][1] + by;
                float v10 = acc[mt][nt][2] + bx, v11 = acc[mt][nt][3] + by;
                int nn = n - 2560;
                int head = nn >> 7, d = nn & 127;
                __half* op = vout + (size_t)(((bb * NHKV + head) * S_LEN + ss) * HD + d);
                *(__half2*)op = __floats2half2_rn(v00, v01);
                *(__half2*)(op + 8 * HD) = __floats2half2_rn(v10, v11);
            }
        }
        return;
    }

    // Q or K region: stage acc+bias (fp32) into smem, then rope -> fp16.
#pragma unroll
    for (int mt = 0; mt < 4; mt++) {
#pragma unroll
        for (int nt = 0; nt < 8; nt++) {
            int mloc = wm + mt * 16 + er;
            int nloc = wn + nt * 8 + ec;
            int n = n0 + nloc;
            float bx = bias[n], by = bias[n + 1];
            float2 a; a.x = acc[mt][nt][0] + bx; a.y = acc[mt][nt][1] + by;
            float2 b; b.x = acc[mt][nt][2] + bx; b.y = acc[mt][nt][3] + by;
            *(float2*)(smf + mloc * EPI_STR + nloc) = a;
            *(float2*)(smf + (mloc + 8) * EPI_STR + nloc) = b;
        }
    }
    __syncthreads();

    const bool isQ = (n0 < 2048);
    const float scale = isQ ? 0.08838834764831845f : 1.0f;
    const int head = isQ ? (n0 >> 7) : ((n0 - 2048) >> 7);
    const int NH   = isQ ? NHQ : NHKV;
    __half* outp   = isQ ? qout : kout;

    // 128 rows x 64 pairs; 128 threads x 64 iterations.
#pragma unroll 4
    for (int i = 0; i < 64; i++) {
        int idx = t + i * 128;
        int row = idx >> 6;          // 0..127
        int pr  = idx & 63;          // pair index (d in [0,64))
        int m = m0 + row;
        int bb = m >> 11, ss = m & 2047;

        float p   = (float)pos_ids[bb * S_LEN + ss];
        float inv = expf(-(float)pr * (13.815510557964274f / 64.0f));
        float ph  = p * inv;
        float c, sn;
        sincosf(ph, &sn, &c);

        float x1 = smf[row * EPI_STR + pr];
        float x2 = smf[row * EPI_STR + pr + 64];
        float y1 = (x1 * c - x2 * sn) * scale;
        float y2 = (x2 * c + x1 * sn) * scale;

        size_t base = (size_t)(((bb * NH + head) * S_LEN + ss) * HD);
        outp[base + pr]      = __float2half_rn(y1);
        outp[base + 64 + pr] = __float2half_rn(y2);
    }
}

// O-projection: row-major fp32, no bias.
__global__ __launch_bounds__(GEMM_THREADS) void tc_gemm_o_kernel(
    const __half* __restrict__ Ap, const __half* __restrict__ Bp,
    float* __restrict__ out)
{
    extern __shared__ char smem[];
    const uint32_t s_u32 = smem_to_u32(smem);
    const int t    = threadIdx.x;
    const int wid  = t >> 5;
    const int lane = t & 31;
    const int m0   = blockIdx.y * 128;
    const int n0   = blockIdx.x * 128;
    const int wm   = (wid >> 1) * 64;
    const int wn   = (wid & 1) * 64;

    float acc[4][8][4];
#pragma unroll
    for (int a = 0; a < 4; a++)
#pragma unroll
        for (int b = 0; b < 8; b++)
#pragma unroll
            for (int c = 0; c < 4; c++) acc[a][b][c] = 0.0f;

    gemm_mainloop(s_u32, Ap, Bp, m0, n0, HDIM, t, lane, wm, wn, acc);

    const int er = lane >> 2;
    const int ec = (lane & 3) * 2;
#pragma unroll
    for (int mt = 0; mt < 4; mt++) {
#pragma unroll
        for (int nt = 0; nt < 8; nt++) {
            int mloc = wm + mt * 16 + er;
            int nloc = wn + nt * 8 + ec;
            int m = m0 + mloc;
            float* op = out + (size_t)m * HDIM + n0 + nloc;
            float2 a; a.x = acc[mt][nt][0]; a.y = acc[mt][nt][1];
            float2 b; b.x = acc[mt][nt][2]; b.y = acc[mt][nt][3];
            *(float2*)op = a;
            *(float2*)(op + 8 * HDIM) = b;
        }
    }
}

// ---------------------------------------------------------------------------
// Tensor-core flash attention, fp16, causal, GQA (unchanged from R14).
// BM=128, BN=64, 8 warps. V natural layout + ldmatrix.trans for PV.
// K/V tiles double-buffered with cp.async; heavy q-tiles first.
// ---------------------------------------------------------------------------
#define FQ_STR 136
#define FK_STR 136
#define SQ_OFF 0
#define KV_OFF (128 * FQ_STR)            // elems
#define KV_STAGE (2 * 64 * FK_STR)       // K tile + V tile per stage, elems
#define FLASH_SMEM_ELEMS (KV_OFF + 2 * KV_STAGE)
#define FLASH_SMEM_BYTES (FLASH_SMEM_ELEMS * 2)   // 104448 B

__device__ __forceinline__ void flash_load_kv(
    uint32_t s_u32, int stage_elems,
    const __half* __restrict__ Kp, const __half* __restrict__ Vp,
    int j, int t)
{
#pragma unroll
    for (int i = 0; i < 4; i++) {
        int chunk = t + i * 256;           // 0..1023
        int row = chunk >> 4;              // 0..63
        int cg  = chunk & 15;
        uint32_t kd = s_u32 + (stage_elems + row * FK_STR + cg * 8) * 2;
        uint32_t vd = kd + (64 * FK_STR) * 2;
        CP_ASYNC16(kd, Kp + (size_t)(j * 64 + row) * HD + cg * 8);
        CP_ASYNC16(vd, Vp + (size_t)(j * 64 + row) * HD + cg * 8);
    }
}

__global__ __launch_bounds__(256) void flash16_kernel(
    const __half* __restrict__ Qg, const __half* __restrict__ Kg,
    const __half* __restrict__ Vg, __half* __restrict__ Ag)
{
    extern __shared__ __align__(16) __half sb[];
    const uint32_t s_u32 = smem_to_u32(sb);

    const int iq = (int)gridDim.x - 1 - (int)blockIdx.x;
    const int h  = blockIdx.y;
    const int b  = blockIdx.z;
    const int hkv = h >> 2;
    const int q0 = iq * 128;
    const int t    = threadIdx.x;
    const int wid  = t >> 5;
    const int lane = t & 31;

    const __half* Qp = Qg + (size_t)((b * NHQ + h) * S_LEN + q0) * HD;
    const __half* Kp = Kg + (size_t)((b * NHKV + hkv) * S_LEN) * HD;
    const __half* Vp = Vg + (size_t)((b * NHKV + hkv) * S_LEN) * HD;

#pragma unroll
    for (int i = 0; i < 8; i++) {
        int chunk = t + i * 256;
        int row = chunk >> 4;
        int cg  = chunk & 15;
        CP_ASYNC16(s_u32 + (SQ_OFF + row * FQ_STR + cg * 8) * 2,
                   Qp + (size_t)row * HD + cg * 8);
    }
    flash_load_kv(s_u32, KV_OFF, Kp, Vp, 0, t);
    CP_COMMIT();

    float o[16][4];
#pragma unroll
    for (int f = 0; f < 16; f++)
#pragma unroll
        for (int e = 0; e < 4; e++) o[f][e] = 0.0f;
    float m0 = -1e30f, m1 = -1e30f, l0 = 0.0f, l1 = 0.0f;

    const int a_row_l = lane & 15;
    const int a_col_l = (lane >> 4) * 8;
    const int b_row_l = ((lane >> 4) << 3) + (lane & 7);
    const int b_col_l = ((lane >> 3) & 1) * 8;
    const int er = lane >> 2;
    const int ec = (lane & 3) * 2;
    const int r0g = q0 + wid * 16 + er;
    const int r1g = r0g + 8;

    const int ntiles = (iq + 1) * 2;

    for (int j = 0; j < ntiles; j++) {
        int buf = j & 1;
        if (j + 1 < ntiles) {
            flash_load_kv(s_u32, KV_OFF + (buf ^ 1) * KV_STAGE, Kp, Vp, j + 1, t);
            CP_COMMIT();
            CP_WAIT(1);
        } else {
            CP_WAIT(0);
        }
        __syncthreads();

        const int skv = KV_OFF + buf * KV_STAGE;      // K tile base (elems)
        const int sv  = skv + 64 * FK_STR;            // V tile base

        // S = Q K^T
        float c[8][4];
#pragma unroll
        for (int nf = 0; nf < 8; nf++)
#pragma unroll
            for (int e = 0; e < 4; e++) c[nf][e] = 0.0f;

#pragma unroll
        for (int kh = 0; kh < 8; kh++) {
            uint32_t ah[4];
            uint32_t ad = s_u32 + (SQ_OFF + (wid * 16 + a_row_l) * FQ_STR +
                                   kh * 16 + a_col_l) * 2;
            ldsm_x4(ah, ad);
#pragma unroll
            for (int np = 0; np < 4; np++) {
                uint32_t bh[4];
                uint32_t bd = s_u32 + (skv + (np * 16 + b_row_l) * FK_STR +
                                       kh * 16 + b_col_l) * 2;
                ldsm_x4(bh, bd);
                mma16816(c[np * 2],     ah, &bh[0]);
                mma16816(c[np * 2 + 1], ah, &bh[2]);
            }
        }

        // Causal mask
        if (j >= 2 * iq) {
#pragma unroll
            for (int nf = 0; nf < 8; nf++) {
#pragma unroll
                for (int d = 0; d < 2; d++) {
                    int col = j * 64 + nf * 8 + ec + d;
                    if (col > r0g) c[nf][d]     = -1e30f;
                    if (col > r1g) c[nf][2 + d] = -1e30f;
                }
            }
        }

        // Online softmax
        float mx0 = -1e30f, mx1 = -1e30f;
#pragma unroll
        for (int nf = 0; nf < 8; nf++) {
            mx0 = fmaxf(mx0, fmaxf(c[nf][0], c[nf][1]));
            mx1 = fmaxf(mx1, fmaxf(c[nf][2], c[nf][3]));
        }
        mx0 = fmaxf(mx0, __shfl_xor_sync(0xffffffffu, mx0, 1));
        mx0 = fmaxf(mx0, __shfl_xor_sync(0xffffffffu, mx0, 2));
        mx1 = fmaxf(mx1, __shfl_xor_sync(0xffffffffu, mx1, 1));
        mx1 = fmaxf(mx1, __shfl_xor_sync(0xffffffffu, mx1, 2));

        float nm0 = fmaxf(m0, mx0), nm1 = fmaxf(m1, mx1);
        float al0 = __expf(m0 - nm0), al1 = __expf(m1 - nm1);
        m0 = nm0; m1 = nm1;

        float s0 = 0.0f, s1 = 0.0f;
#pragma unroll
        for (int nf = 0; nf < 8; nf++) {
            c[nf][0] = __expf(c[nf][0] - nm0);
            c[nf][1] = __expf(c[nf][1] - nm0);
            c[nf][2] = __expf(c[nf][2] - nm1);
            c[nf][3] = __expf(c[nf][3] - nm1);
            s0 += c[nf][0] + c[nf][1];
            s1 += c[nf][2] + c[nf][3];
        }
        s0 += __shfl_xor_sync(0xffffffffu, s0, 1);
        s0 += __shfl_xor_sync(0xffffffffu, s0, 2);
        s1 += __shfl_xor_sync(0xffffffffu, s1, 1);
        s1 += __shfl_xor_sync(0xffffffffu, s1, 2);
        l0 = l0 * al0 + s0;
        l1 = l1 * al1 + s1;

#pragma unroll
        for (int f = 0; f < 16; f++) {
            o[f][0] *= al0; o[f][1] *= al0;
            o[f][2] *= al1; o[f][3] *= al1;
        }

        // P @ V with trans-loaded B fragments from natural V layout
#pragma unroll
        for (int kf = 0; kf < 4; kf++) {
            int nf0 = kf * 2, nf1 = kf * 2 + 1;
            uint32_t pa[4];
            pa[0] = pack_h2(c[nf0][0], c[nf0][1]);
            pa[1] = pack_h2(c[nf0][2], c[nf0][3]);
            pa[2] = pack_h2(c[nf1][0], c[nf1][1]);
            pa[3] = pack_h2(c[nf1][2], c[nf1][3]);
#pragma unroll
            for (int nt = 0; nt < 8; nt++) {
                uint32_t bv[4];
                uint32_t bd = s_u32 + (sv + (kf * 16 + (lane & 15)) * FK_STR +
                                       nt * 16 + (lane >> 4) * 8) * 2;
                ldsm_x4_trans(bv, bd);
                mma16816(o[nt * 2],     pa, &bv[0]);
                mma16816(o[nt * 2 + 1], pa, &bv[2]);
            }
        }
        __syncthreads();
    }

    // Epilogue: fp16 row-major [m, h*128 + d]
    float inv0 = 1.0f / l0, inv1 = 1.0f / l1;
    __half* Ap0 = Ag + (size_t)(b * S_LEN + r0g) * HDIM + h * HD;
    __half* Ap1 = Ag + (size_t)(b * S_LEN + r1g) * HDIM + h * HD;
#pragma unroll
    for (int f = 0; f < 16; f++) {
        int col = (f >> 1) * 16 + (f & 1) * 8 + ec;
        __half2 v0 = __floats2half2_rn(o[f][0] * inv0, o[f][1] * inv0);
        __half2 v1 = __floats2half2_rn(o[f][2] * inv1, o[f][3] * inv1);
        *(__half2*)(Ap0 + col) = v0;
        *(__half2*)(Ap1 + col) = v1;
    }
}

// ---------------------------------------------------------------------------
// Launch
// ---------------------------------------------------------------------------
extern "C" void kernel_launch(void* const* d_in, const int* in_sizes, int n_in,
                              void* d_out, int out_size)
{
    const float* hs = (const float*)d_in[0];
    const float* wq = (const float*)d_in[1];
    const float* bq = (const float*)d_in[2];
    const float* wk = (const float*)d_in[3];
    const float* bk = (const float*)d_in[4];
    const float* wv = (const float*)d_in[5];
    const float* bv = (const float*)d_in[6];
    const float* wo = (const float*)d_in[7];
    const int*  pos = (const int*)d_in[8];
    float* out = (float*)d_out;

    float *bqkv;
    cudaGetSymbolAddress((void**)&bqkv, g_bqkv);

    __half *x16, *wqkv16, *wo16, *qh16, *kh16, *vh16, *a16;
    cudaGetSymbolAddress((void**)&x16,    g_x16);
    cudaGetSymbolAddress((void**)&wqkv16, g_wqkv16);
    cudaGetSymbolAddress((void**)&wo16,   g_wo16);
    cudaGetSymbolAddress((void**)&qh16,   g_qh16);
    cudaGetSymbolAddress((void**)&kh16,   g_kh16);
    cudaGetSymbolAddress((void**)&vh16,   g_vh16);
    cudaGetSymbolAddress((void**)&a16,    g_a16);

    cudaFuncSetAttribute(flash16_kernel,
                         cudaFuncAttributeMaxDynamicSharedMemorySize, FLASH_SMEM_BYTES);
    cudaFuncSetAttribute(tc_gemm_qkv_kernel,
                         cudaFuncAttributeMaxDynamicSharedMemorySize, GEMM_SMEM);
    cudaFuncSetAttribute(tc_gemm_o_kernel,
                         cudaFuncAttributeMaxDynamicSharedMemorySize, GEMM_SMEM);

    // 1. Convert inputs to fp16 (weights into concat buffer) + concat biases
    {
        int n4x = (M_ROWS * HDIM) / 4;
        cvt_h_kernel<<<(n4x + 255) / 256, 256>>>(hs, x16, n4x);
        int n4q = (HDIM * HDIM) / 4;
        cvt_h_kernel<<<(n4q + 255) / 256, 256>>>(wq, wqkv16, n4q);
        int n4k = (NHKV * HD * HDIM) / 4;
        cvt_h_kernel<<<(n4k + 255) / 256, 256>>>(wk, wqkv16 + 2048 * HDIM, n4k);
        cvt_h_kernel<<<(n4k + 255) / 256, 256>>>(wv, wqkv16 + 2560 * HDIM, n4k);
        cvt_h_kernel<<<(n4q + 255) / 256, 256>>>(wo, wo16, n4q);
        cudaMemcpyAsync(bqkv,        bq, 2048 * 4, cudaMemcpyDeviceToDevice, 0);
        cudaMemcpyAsync(bqkv + 2048, bk,  512 * 4, cudaMemcpyDeviceToDevice, 0);
        cudaMemcpyAsync(bqkv + 2560, bv,  512 * 4, cudaMemcpyDeviceToDevice, 0);
    }

    // 2. Fused QKV projection + RoPE (768 CTAs, 128 threads each)
    tc_gemm_qkv_kernel<<<dim3(NQKV / 128, M_ROWS / 128), GEMM_THREADS, GEMM_SMEM>>>(
        x16, wqkv16, bqkv, pos, qh16, kh16, vh16);

    // 3. Flash attention (fp16 MMA), heavy tiles first
    flash16_kernel<<<dim3(S_LEN / 128, NHQ, BATCH), 256, FLASH_SMEM_BYTES>>>(
        qh16, kh16, vh16, a16);

    // 4. O-projection -> d_out (row-major fp32)
    tc_gemm_o_kernel<<<dim3(HDIM / 128, M_ROWS / 128), GEMM_THREADS, GEMM_SMEM>>>(
        a16, wo16, out);
}

// round 16
// speedup vs baseline: 1.0810x; 1.0238x over previous
#include <cuda_runtime.h>
#include <cuda_fp16.h>
#include <math.h>
#include <cstdint>

// Problem constants
#define S_LEN 2048
#define HDIM  2048
#define NHQ   16
#define NHKV  4
#define HD    128
#define BATCH 2
#define M_ROWS (BATCH * S_LEN)   // 4096
#define NQKV  3072               // 2048 (Q) + 512 (K) + 512 (V)

// ---------------------------------------------------------------------------
// Scratch (allocation-free: __device__ globals)
// ---------------------------------------------------------------------------
__device__ __half g_x16[M_ROWS * HDIM];             // hidden fp16
__device__ __half g_wqkv16[NQKV * HDIM];            // concat Wq|Wk|Wv fp16
__device__ __half g_wo16[HDIM * HDIM];
__device__ float  g_bqkv[NQKV];                     // concat bq|bk|bv
__device__ __half g_qh16[BATCH * NHQ * S_LEN * HD];   // post-RoPE Q (scaled)
__device__ __half g_kh16[BATCH * NHKV * S_LEN * HD];  // post-RoPE K
__device__ __half g_vh16[BATCH * NHKV * S_LEN * HD];  // V fp16 (direct)
__device__ __half g_a16[M_ROWS * HDIM];               // attn out, row-major

// ---------------------------------------------------------------------------
// PTX helpers
// ---------------------------------------------------------------------------
__device__ __forceinline__ uint32_t smem_to_u32(const void* smem_ptr) {
    uint32_t addr;
    asm("{ .reg .u64 tmp; cvta.to.shared.u64 tmp, %1; cvt.u32.u64 %0, tmp; }"
        : "=r"(addr) : "l"(smem_ptr));
    return addr;
}

__device__ __forceinline__ void ldsm_x4(uint32_t* r, uint32_t addr) {
    asm volatile("ldmatrix.sync.aligned.m8n8.x4.shared.b16 {%0,%1,%2,%3}, [%4];"
                 : "=r"(r[0]), "=r"(r[1]), "=r"(r[2]), "=r"(r[3]) : "r"(addr));
}

__device__ __forceinline__ void ldsm_x4_trans(uint32_t* r, uint32_t addr) {
    asm volatile("ldmatrix.sync.aligned.m8n8.x4.trans.shared.b16 {%0,%1,%2,%3}, [%4];"
                 : "=r"(r[0]), "=r"(r[1]), "=r"(r[2]), "=r"(r[3]) : "r"(addr));
}

__device__ __forceinline__ void mma16816(float* d, const uint32_t* a,
                                         const uint32_t* b) {
    asm volatile(
        "mma.sync.aligned.m16n8k16.row.col.f32.f16.f16.f32 "
        "{%0,%1,%2,%3}, {%4,%5,%6,%7}, {%8,%9}, {%0,%1,%2,%3};"
        : "+f"(d[0]), "+f"(d[1]), "+f"(d[2]), "+f"(d[3])
        : "r"(a[0]), "r"(a[1]), "r"(a[2]), "r"(a[3]), "r"(b[0]), "r"(b[1]));
}

#define CP_ASYNC16(dst_u32, src_ptr) \
    asm volatile("cp.async.cg.shared.global [%0], [%1], 16;" \
                 :: "r"(dst_u32), "l"(src_ptr))
#define CP_COMMIT() asm volatile("cp.async.commit_group;" ::: "memory")
#define CP_WAIT(n)  asm volatile("cp.async.wait_group %0;" :: "n"(n) : "memory")

__device__ __forceinline__ uint32_t pack_h2(float x, float y) {
    __half2 t = __floats2half2_rn(x, y);
    return *(uint32_t*)&t;
}

// ---------------------------------------------------------------------------
// ONE setup kernel: all fp32->fp16 conversions + bias concat.
// Block-granular regions (256 threads x f4 elements). Region sizes in f4:
//   x : 2,097,152/4 = 524288? no: M_ROWS*HDIM/4 = 2,097,152 f4? (4096*2048/4)=2,097,152/..
// Just use macros.
// ---------------------------------------------------------------------------
#define CV_X  (M_ROWS * HDIM / 4)        // 2097152 f4? = 4096*2048/4 = 2097152
#define CV_WQ (HDIM * HDIM / 4)          // 1048576
#define CV_WK (512 * HDIM / 4)           // 262144
#define CV_B0 CV_X
#define CV_B1 (CV_B0 + CV_WQ)
#define CV_B2 (CV_B1 + CV_WK)
#define CV_B3 (CV_B2 + CV_WK)
#define CV_B4 (CV_B3 + CV_WQ)
#define CV_TOTAL (CV_B4 + (NQKV / 4))    // + bias concat (768 f4)

__device__ __forceinline__ void cvt4(const float* __restrict__ in,
                                     __half* __restrict__ out, int j)
{
    float4 v = ((const float4*)in)[j];
    ((__half2*)out)[2 * j]     = __floats2half2_rn(v.x, v.y);
    ((__half2*)out)[2 * j + 1] = __floats2half2_rn(v.z, v.w);
}

__global__ void setup_kernel(const float* __restrict__ hs,
                             const float* __restrict__ wq,
                             const float* __restrict__ wk,
                             const float* __restrict__ wv,
                             const float* __restrict__ wo,
                             const float* __restrict__ bq,
                             const float* __restrict__ bk,
                             const float* __restrict__ bv,
                             __half* __restrict__ x16,
                             __half* __restrict__ wqkv16,
                             __half* __restrict__ wo16,
                             float* __restrict__ bqkv)
{
    int i = blockIdx.x * 256 + threadIdx.x;
    if (i < CV_B0) {
        cvt4(hs, x16, i);
    } else if (i < CV_B1) {
        cvt4(wq, wqkv16, i - CV_B0);
    } else if (i < CV_B2) {
        cvt4(wk, wqkv16 + 2048 * HDIM, i - CV_B1);
    } else if (i < CV_B3) {
        cvt4(wv, wqkv16 + 2560 * HDIM, i - CV_B2);
    } else if (i < CV_B4) {
        cvt4(wo, wo16, i - CV_B3);
    } else if (i < CV_TOTAL) {
        int j = i - CV_B4;               // 0..767 (f4 over 3072 floats)
        int e = j * 4;
        float4 v;
        if (e < 2048)        v = *(const float4*)(bq + e);
        else if (e < 2560)   v = *(const float4*)(bk + (e - 2048));
        else                 v = *(const float4*)(bv + (e - 2560));
        *(float4*)(bqkv + e) = v;
    }
}

// ---------------------------------------------------------------------------
// GEMM core: block 128x128, BK=32, 4 warps (2m x 2n), warp tile 64x64,
// 128 threads, 3-stage cp.async pipeline. MMA:ldsm ratio 4.0.  (R12-proven)
// ---------------------------------------------------------------------------
#define MATB (128 * 80)              // 10240 B per matrix tile
#define STAGEB (2 * MATB)            // A + B = 20480 B
#define NSTAGE 3
#define EPI_STR 132                  // fp32 epilogue smem row stride (floats)
#define EPI_BYTES (128 * EPI_STR * 4)             // 67584
#define GEMM_SMEM (EPI_BYTES)        // >= NSTAGE*STAGEB (61440); epilogue reuse
#define GEMM_THREADS 128

__device__ __forceinline__ void gemm_copy_stage(
    uint32_t s_u32,
    const __half* __restrict__ Ap, const __half* __restrict__ Bp,
    int m0, int n0, int k0, int Kdim, int t)
{
#pragma unroll
    for (int i = 0; i < 4; i++) {
        int chunk = t + i * GEMM_THREADS;      // 0..511
        int row = chunk >> 2;
        int ch  = chunk & 3;
        uint32_t dst = s_u32 + row * 80 + ch * 16;
        size_t aoff = (size_t)(m0 + row) * Kdim + k0 + ch * 8;
        size_t boff = (size_t)(n0 + row) * Kdim + k0 + ch * 8;
        CP_ASYNC16(dst,        Ap + aoff);
        CP_ASYNC16(dst + MATB, Bp + boff);
    }
}

// Mainloop: fills acc[4][8][4] (warp tile 64x64).
__device__ __forceinline__ void gemm_mainloop(
    uint32_t s_u32, const __half* Ap, const __half* Bp,
    int m0, int n0, int Kdim, int t, int lane,
    int wm, int wn, float acc[4][8][4])
{
    const int nsteps = Kdim >> 5;
    const int a_row_l = lane & 15;
    const int a_col_l = (lane >> 4) * 8;
    const int b_row_l = ((lane >> 4) << 3) + (lane & 7);
    const int b_col_l = ((lane >> 3) & 1) * 8;

    // Prologue: stages 0, 1
    gemm_copy_stage(s_u32,          Ap, Bp, m0, n0, 0,  Kdim, t);
    CP_COMMIT();
    gemm_copy_stage(s_u32 + STAGEB, Ap, Bp, m0, n0, 32, Kdim, t);
    CP_COMMIT();

    int buf = 0;
    for (int s = 0; s < nsteps; s++) {
        if (s + 1 < nsteps) { CP_WAIT(1); } else { CP_WAIT(0); }
        __syncthreads();

        if (s + 2 < nsteps) {
            int nb = buf + 2; if (nb >= NSTAGE) nb -= NSTAGE;
            gemm_copy_stage(s_u32 + nb * STAGEB, Ap, Bp,
                            m0, n0, (s + 2) << 5, Kdim, t);
            CP_COMMIT();
        }

        uint32_t sA = s_u32 + buf * STAGEB;
        uint32_t sB = sA + MATB;

#pragma unroll
        for (int kh = 0; kh < 2; kh++) {
            uint32_t af[4][4], bf[4][4];
#pragma unroll
            for (int mt = 0; mt < 4; mt++) {
                uint32_t ad = sA + (wm + mt * 16 + a_row_l) * 80 +
                              (kh * 16 + a_col_l) * 2;
                ldsm_x4(af[mt], ad);
            }
#pragma unroll
            for (int np = 0; np < 4; np++) {
                uint32_t bd = sB + (wn + np * 16 + b_row_l) * 80 +
                              (kh * 16 + b_col_l) * 2;
                ldsm_x4(bf[np], bd);
            }
#pragma unroll
            for (int mt = 0; mt < 4; mt++) {
#pragma unroll
                for (int np = 0; np < 4; np++) {
                    mma16816(acc[mt][np * 2],     af[mt], &bf[np][0]);
                    mma16816(acc[mt][np * 2 + 1], af[mt], &bf[np][2]);
                }
            }
        }
        __syncthreads();
        buf++; if (buf == NSTAGE) buf = 0;
    }
}

// Fused QKV projection + RoPE.
// N-regions: [0,2048)=Q (rope, scale, fp16), [2048,2560)=K (rope, fp16),
// [2560,3072)=V (fp16 direct). Each 128-col block = one head.
__global__ __launch_bounds__(GEMM_THREADS) void tc_gemm_qkv_kernel(
    const __half* __restrict__ Ap, const __half* __restrict__ Bp,
    const float* __restrict__ bias, const int* __restrict__ pos_ids,
    __half* __restrict__ qout, __half* __restrict__ kout,
    __half* __restrict__ vout)
{
    extern __shared__ char smem[];
    const uint32_t s_u32 = smem_to_u32(smem);
    float* smf = (float*)smem;
    const int t    = threadIdx.x;
    const int wid  = t >> 5;
    const int lane = t & 31;
    const int m0   = blockIdx.y * 128;
    const int n0   = blockIdx.x * 128;
    const int wm   = (wid >> 1) * 64;
    const int wn   = (wid & 1) * 64;

    float acc[4][8][4];
#pragma unroll
    for (int a = 0; a < 4; a++)
#pragma unroll
        for (int b = 0; b < 8; b++)
#pragma unroll
            for (int c = 0; c < 4; c++) acc[a][b][c] = 0.0f;

    gemm_mainloop(s_u32, Ap, Bp, m0, n0, HDIM, t, lane, wm, wn, acc);

    const int er = lane >> 2;
    const int ec = (lane & 3) * 2;

    if (n0 >= 2560) {
        // V region -> fp16 head-major direct
#pragma unroll
        for (int mt = 0; mt < 4; mt++) {
#pragma unroll
            for (int nt = 0; nt < 8; nt++) {
                int mloc = wm + mt * 16 + er;
                int nloc = wn + nt * 8 + ec;
                int m = m0 + mloc;
                int n = n0 + nloc;
                int bb = m >> 11, ss = m & 2047;
                float bx = bias[n], by = bias[n + 1];
                float v00 = acc[mt][nt][0] + bx, v01 = acc[mt][nt][1] + by;
                float v10 = acc[mt][nt][2] + bx, v11 = acc[mt][nt][3] + by;
                int nn = n - 2560;
                int head = nn >> 7, d = nn & 127;
                __half* op = vout + (size_t)(((bb * NHKV + head) * S_LEN + ss) * HD + d);
                *(__half2*)op = __floats2half2_rn(v00, v01);
                *(__half2*)(op + 8 * HD) = __floats2half2_rn(v10, v11);
            }
        }
        return;
    }

    // Q or K region: stage acc+bias (fp32) into smem, then rope -> fp16.
#pragma unroll
    for (int mt = 0; mt < 4; mt++) {
#pragma unroll
        for (int nt = 0; nt < 8; nt++) {
            int mloc = wm + mt * 16 + er;
            int nloc = wn + nt * 8 + ec;
            int n = n0 + nloc;
            float bx = bias[n], by = bias[n + 1];
            float2 a; a.x = acc[mt][nt][0] + bx; a.y = acc[mt][nt][1] + by;
            float2 b; b.x = acc[mt][nt][2] + bx; b.y = acc[mt][nt][3] + by;
            *(float2*)(smf + mloc * EPI_STR + nloc) = a;
            *(float2*)(smf + (mloc + 8) * EPI_STR + nloc) = b;
        }
    }
    __syncthreads();

    const bool isQ = (n0 < 2048);
    const float scale = isQ ? 0.08838834764831845f : 1.0f;
    const int head = isQ ? (n0 >> 7) : ((n0 - 2048) >> 7);
    const int NH   = isQ ? NHQ : NHKV;
    __half* outp   = isQ ? qout : kout;

    // 128 rows x 64 pairs; 128 threads x 64 iterations.
#pragma unroll 4
    for (int i = 0; i < 64; i++) {
        int idx = t + i * 128;
        int row = idx >> 6;          // 0..127
        int pr  = idx & 63;          // pair index (d in [0,64))
        int m = m0 + row;
        int bb = m >> 11, ss = m & 2047;

        float p   = (float)pos_ids[bb * S_LEN + ss];
        float inv = expf(-(float)pr * (13.815510557964274f / 64.0f));
        float ph  = p * inv;
        float c, sn;
        sincosf(ph, &sn, &c);

        float x1 = smf[row * EPI_STR + pr];
        float x2 = smf[row * EPI_STR + pr + 64];
        float y1 = (x1 * c - x2 * sn) * scale;
        float y2 = (x2 * c + x1 * sn) * scale;

        size_t base = (size_t)(((bb * NH + head) * S_LEN + ss) * HD);
        outp[base + pr]      = __float2half_rn(y1);
        outp[base + 64 + pr] = __float2half_rn(y2);
    }
}

// O-projection: row-major fp32, no bias.
__global__ __launch_bounds__(GEMM_THREADS) void tc_gemm_o_kernel(
    const __half* __restrict__ Ap, const __half* __restrict__ Bp,
    float* __restrict__ out)
{
    extern __shared__ char smem[];
    const uint32_t s_u32 = smem_to_u32(smem);
    const int t    = threadIdx.x;
    const int wid  = t >> 5;
    const int lane = t & 31;
    const int m0   = blockIdx.y * 128;
    const int n0   = blockIdx.x * 128;
    const int wm   = (wid >> 1) * 64;
    const int wn   = (wid & 1) * 64;

    float acc[4][8][4];
#pragma unroll
    for (int a = 0; a < 4; a++)
#pragma unroll
        for (int b = 0; b < 8; b++)
#pragma unroll
            for (int c = 0; c < 4; c++) acc[a][b][c] = 0.0f;

    gemm_mainloop(s_u32, Ap, Bp, m0, n0, HDIM, t, lane, wm, wn, acc);

    const int er = lane >> 2;
    const int ec = (lane & 3) * 2;
#pragma unroll
    for (int mt = 0; mt < 4; mt++) {
#pragma unroll
        for (int nt = 0; nt < 8; nt++) {
            int mloc = wm + mt * 16 + er;
            int nloc = wn + nt * 8 + ec;
            int m = m0 + mloc;
            float* op = out + (size_t)m * HDIM + n0 + nloc;
            float2 a; a.x = acc[mt][nt][0]; a.y = acc[mt][nt][1];
            float2 b; b.x = acc[mt][nt][2]; b.y = acc[mt][nt][3];
            *(float2*)op = a;
            *(float2*)(op + 8 * HDIM) = b;
        }
    }
}

// ---------------------------------------------------------------------------
// Tensor-core flash attention, fp16, causal, GQA (unchanged, proven).
// BM=128, BN=64, 8 warps. V natural layout + ldmatrix.trans for PV.
// K/V tiles double-buffered with cp.async; heavy q-tiles first.
// ---------------------------------------------------------------------------
#define FQ_STR 136
#define FK_STR 136
#define SQ_OFF 0
#define KV_OFF (128 * FQ_STR)            // elems
#define KV_STAGE (2 * 64 * FK_STR)       // K tile + V tile per stage, elems
#define FLASH_SMEM_ELEMS (KV_OFF + 2 * KV_STAGE)
#define FLASH_SMEM_BYTES (FLASH_SMEM_ELEMS * 2)   // 104448 B

__device__ __forceinline__ void flash_load_kv(
    uint32_t s_u32, int stage_elems,
    const __half* __restrict__ Kp, const __half* __restrict__ Vp,
    int j, int t)
{
#pragma unroll
    for (int i = 0; i < 4; i++) {
        int chunk = t + i * 256;           // 0..1023
        int row = chunk >> 4;              // 0..63
        int cg  = chunk & 15;
        uint32_t kd = s_u32 + (stage_elems + row * FK_STR + cg * 8) * 2;
        uint32_t vd = kd + (64 * FK_STR) * 2;
        CP_ASYNC16(kd, Kp + (size_t)(j * 64 + row) * HD + cg * 8);
        CP_ASYNC16(vd, Vp + (size_t)(j * 64 + row) * HD + cg * 8);
    }
}

__global__ __launch_bounds__(256) void flash16_kernel(
    const __half* __restrict__ Qg, const __half* __restrict__ Kg,
    const __half* __restrict__ Vg, __half* __restrict__ Ag)
{
    extern __shared__ __align__(16) __half sb[];
    const uint32_t s_u32 = smem_to_u32(sb);

    const int iq = (int)gridDim.x - 1 - (int)blockIdx.x;
    const int h  = blockIdx.y;
    const int b  = blockIdx.z;
    const int hkv = h >> 2;
    const int q0 = iq * 128;
    const int t    = threadIdx.x;
    const int wid  = t >> 5;
    const int lane = t & 31;

    const __half* Qp = Qg + (size_t)((b * NHQ + h) * S_LEN + q0) * HD;
    const __half* Kp = Kg + (size_t)((b * NHKV + hkv) * S_LEN) * HD;
    const __half* Vp = Vg + (size_t)((b * NHKV + hkv) * S_LEN) * HD;

#pragma unroll
    for (int i = 0; i < 8; i++) {
        int chunk = t + i * 256;
        int row = chunk >> 4;
        int cg  = chunk & 15;
        CP_ASYNC16(s_u32 + (SQ_OFF + row * FQ_STR + cg * 8) * 2,
                   Qp + (size_t)row * HD + cg * 8);
    }
    flash_load_kv(s_u32, KV_OFF, Kp, Vp, 0, t);
    CP_COMMIT();

    float o[16][4];
#pragma unroll
    for (int f = 0; f < 16; f++)
#pragma unroll
        for (int e = 0; e < 4; e++) o[f][e] = 0.0f;
    float m0 = -1e30f, m1 = -1e30f, l0 = 0.0f, l1 = 0.0f;

    const int a_row_l = lane & 15;
    const int a_col_l = (lane >> 4) * 8;
    const int b_row_l = ((lane >> 4) << 3) + (lane & 7);
    const int b_col_l = ((lane >> 3) & 1) * 8;
    const int er = lane >> 2;
    const int ec = (lane & 3) * 2;
    const int r0g = q0 + wid * 16 + er;
    const int r1g = r0g + 8;

    const int ntiles = (iq + 1) * 2;

    for (int j = 0; j < ntiles; j++) {
        int buf = j & 1;
        if (j + 1 < ntiles) {
            flash_load_kv(s_u32, KV_OFF + (buf ^ 1) * KV_STAGE, Kp, Vp, j + 1, t);
            CP_COMMIT();
            CP_WAIT(1);
        } else {
            CP_WAIT(0);
        }
        __syncthreads();

        const int skv = KV_OFF + buf * KV_STAGE;      // K tile base (elems)
        const int sv  = skv + 64 * FK_STR;            // V tile base

        // S = Q K^T
        float c[8][4];
#pragma unroll
        for (int nf = 0; nf < 8; nf++)
#pragma unroll
            for (int e = 0; e < 4; e++) c[nf][e] = 0.0f;

#pragma unroll
        for (int kh = 0; kh < 8; kh++) {
            uint32_t ah[4];
            uint32_t ad = s_u32 + (SQ_OFF + (wid * 16 + a_row_l) * FQ_STR +
                                   kh * 16 + a_col_l) * 2;
            ldsm_x4(ah, ad);
#pragma unroll
            for (int np = 0; np < 4; np++) {
                uint32_t bh[4];
                uint32_t bd = s_u32 + (skv + (np * 16 + b_row_l) * FK_STR +
                                       kh * 16 + b_col_l) * 2;
                ldsm_x4(bh, bd);
                mma16816(c[np * 2],     ah, &bh[0]);
                mma16816(c[np * 2 + 1], ah, &bh[2]);
            }
        }

        // Causal mask
        if (j >= 2 * iq) {
#pragma unroll
            for (int nf = 0; nf < 8; nf++) {
#pragma unroll
                for (int d = 0; d < 2; d++) {
                    int col = j * 64 + nf * 8 + ec + d;
                    if (col > r0g) c[nf][d]     = -1e30f;
                    if (col > r1g) c[nf][2 + d] = -1e30f;
                }
            }
        }

        // Online softmax
        float mx0 = -1e30f, mx1 = -1e30f;
#pragma unroll
        for (int nf = 0; nf < 8; nf++) {
            mx0 = fmaxf(mx0, fmaxf(c[nf][0], c[nf][1]));
            mx1 = fmaxf(mx1, fmaxf(c[nf][2], c[nf][3]));
        }
        mx0 = fmaxf(mx0, __shfl_xor_sync(0xffffffffu, mx0, 1));
        mx0 = fmaxf(mx0, __shfl_xor_sync(0xffffffffu, mx0, 2));
        mx1 = fmaxf(mx1, __shfl_xor_sync(0xffffffffu, mx1, 1));
        mx1 = fmaxf(mx1, __shfl_xor_sync(0xffffffffu, mx1, 2));

        float nm0 = fmaxf(m0, mx0), nm1 = fmaxf(m1, mx1);
        float al0 = __expf(m0 - nm0), al1 = __expf(m1 - nm1);
        m0 = nm0; m1 = nm1;

        float s0 = 0.0f, s1 = 0.0f;
#pragma unroll
        for (int nf = 0; nf < 8; nf++) {
            c[nf][0] = __expf(c[nf][0] - nm0);
            c[nf][1] = __expf(c[nf][1] - nm0);
            c[nf][2] = __expf(c[nf][2] - nm1);
            c[nf][3] = __expf(c[nf][3] - nm1);
            s0 += c[nf][0] + c[nf][1];
            s1 += c[nf][2] + c[nf][3];
        }
        s0 += __shfl_xor_sync(0xffffffffu, s0, 1);
        s0 += __shfl_xor_sync(0xffffffffu, s0, 2);
        s1 += __shfl_xor_sync(0xffffffffu, s1, 1);
        s1 += __shfl_xor_sync(0xffffffffu, s1, 2);
        l0 = l0 * al0 + s0;
        l1 = l1 * al1 + s1;

#pragma unroll
        for (int f = 0; f < 16; f++) {
            o[f][0] *= al0; o[f][1] *= al0;
            o[f][2] *= al1; o[f][3] *= al1;
        }

        // P @ V with trans-loaded B fragments from natural V layout
#pragma unroll
        for (int kf = 0; kf < 4; kf++) {
            int nf0 = kf * 2, nf1 = kf * 2 + 1;
            uint32_t pa[4];
            pa[0] = pack_h2(c[nf0][0], c[nf0][1]);
            pa[1] = pack_h2(c[nf0][2], c[nf0][3]);
            pa[2] = pack_h2(c[nf1][0], c[nf1][1]);
            pa[3] = pack_h2(c[nf1][2], c[nf1][3]);
#pragma unroll
            for (int nt = 0; nt < 8; nt++) {
                uint32_t bv[4];
                uint32_t bd = s_u32 + (sv + (kf * 16 + (lane & 15)) * FK_STR +
                                       nt * 16 + (lane >> 4) * 8) * 2;
                ldsm_x4_trans(bv, bd);
                mma16816(o[nt * 2],     pa, &bv[0]);
                mma16816(o[nt * 2 + 1], pa, &bv[2]);
            }
        }
        __syncthreads();
    }

    // Epilogue: fp16 row-major [m, h*128 + d]
    float inv0 = 1.0f / l0, inv1 = 1.0f / l1;
    __half* Ap0 = Ag + (size_t)(b * S_LEN + r0g) * HDIM + h * HD;
    __half* Ap1 = Ag + (size_t)(b * S_LEN + r1g) * HDIM + h * HD;
#pragma unroll
    for (int f = 0; f < 16; f++) {
        int col = (f >> 1) * 16 + (f & 1) * 8 + ec;
        __half2 v0 = __floats2half2_rn(o[f][0] * inv0, o[f][1] * inv0);
        __half2 v1 = __floats2half2_rn(o[f][2] * inv1, o[f][3] * inv1);
        *(__half2*)(Ap0 + col) = v0;
        *(__half2*)(Ap1 + col) = v1;
    }
}

// ---------------------------------------------------------------------------
// Launch
// ---------------------------------------------------------------------------
extern "C" void kernel_launch(void* const* d_in, const int* in_sizes, int n_in,
                              void* d_out, int out_size)
{
    const float* hs = (const float*)d_in[0];
    const float* wq = (const float*)d_in[1];
    const float* bq = (const float*)d_in[2];
    const float* wk = (const float*)d_in[3];
    const float* bk = (const float*)d_in[4];
    const float* wv = (const float*)d_in[5];
    const float* bv = (const float*)d_in[6];
    const float* wo = (const float*)d_in[7];
    const int*  pos = (const int*)d_in[8];
    float* out = (float*)d_out;

    float *bqkv;
    cudaGetSymbolAddress((void**)&bqkv, g_bqkv);

    __half *x16, *wqkv16, *wo16, *qh16, *kh16, *vh16, *a16;
    cudaGetSymbolAddress((void**)&x16,    g_x16);
    cudaGetSymbolAddress((void**)&wqkv16, g_wqkv16);
    cudaGetSymbolAddress((void**)&wo16,   g_wo16);
    cudaGetSymbolAddress((void**)&qh16,   g_qh16);
    cudaGetSymbolAddress((void**)&kh16,   g_kh16);
    cudaGetSymbolAddress((void**)&vh16,   g_vh16);
    cudaGetSymbolAddress((void**)&a16,    g_a16);

    cudaFuncSetAttribute(flash16_kernel,
                         cudaFuncAttributeMaxDynamicSharedMemorySize, FLASH_SMEM_BYTES);
    cudaFuncSetAttribute(tc_gemm_qkv_kernel,
                         cudaFuncAttributeMaxDynamicSharedMemorySize, GEMM_SMEM);
    cudaFuncSetAttribute(tc_gemm_o_kernel,
                         cudaFuncAttributeMaxDynamicSharedMemorySize, GEMM_SMEM);

    // 1. ONE setup kernel: all conversions + bias concat
    setup_kernel<<<(CV_TOTAL + 255) / 256, 256>>>(
        hs, wq, wk, wv, wo, bq, bk, bv, x16, wqkv16, wo16, bqkv);

    // 2. Fused QKV projection + RoPE (768 CTAs, 128 threads each)
    tc_gemm_qkv_kernel<<<dim3(NQKV / 128, M_ROWS / 128), GEMM_THREADS, GEMM_SMEM>>>(
        x16, wqkv16, bqkv, pos, qh16, kh16, vh16);

    // 3. Flash attention (fp16 MMA), heavy tiles first
    flash16_kernel<<<dim3(S_LEN / 128, NHQ, BATCH), 256, FLASH_SMEM_BYTES>>>(
        qh16, kh16, vh16, a16);

    // 4. O-projection -> d_out (row-major fp32)
    tc_gemm_o_kernel<<<dim3(HDIM / 128, M_ROWS / 128), GEMM_THREADS, GEMM_SMEM>>>(
        a16, wo16, out);
}

// round 17
// speedup vs baseline: 1.0869x; 1.0054x over previous
#include <cuda_runtime.h>
#include <cuda_fp16.h>
#include <math.h>
#include <cstdint>

// Problem constants
#define S_LEN 2048
#define HDIM  2048
#define NHQ   16
#define NHKV  4
#define HD    128
#define BATCH 2
#define M_ROWS (BATCH * S_LEN)   // 4096
#define NQKV  3072               // 2048 (Q) + 512 (K) + 512 (V)

// ---------------------------------------------------------------------------
// Scratch (allocation-free: __device__ globals)
// ---------------------------------------------------------------------------
__device__ __half g_x16[M_ROWS * HDIM];             // hidden fp16
__device__ __half g_wqkv16[NQKV * HDIM];            // concat Wq|Wk|Wv fp16
__device__ __half g_wo16[HDIM * HDIM];
__device__ float  g_bqkv[NQKV];                     // concat bq|bk|bv
__device__ float  g_rcos[M_ROWS * 64];              // rope cos table [m][pr]
__device__ float  g_rsin[M_ROWS * 64];              // rope sin table [m][pr]
__device__ __half g_qh16[BATCH * NHQ * S_LEN * HD];   // post-RoPE Q (scaled)
__device__ __half g_kh16[BATCH * NHKV * S_LEN * HD];  // post-RoPE K
__device__ __half g_vh16[BATCH * NHKV * S_LEN * HD];  // V fp16 (direct)
__device__ __half g_a16[M_ROWS * HDIM];               // attn out, row-major

// ---------------------------------------------------------------------------
// PTX helpers
// ---------------------------------------------------------------------------
__device__ __forceinline__ uint32_t smem_to_u32(const void* smem_ptr) {
    uint32_t addr;
    asm("{ .reg .u64 tmp; cvta.to.shared.u64 tmp, %1; cvt.u32.u64 %0, tmp; }"
        : "=r"(addr) : "l"(smem_ptr));
    return addr;
}

__device__ __forceinline__ void ldsm_x4(uint32_t* r, uint32_t addr) {
    asm volatile("ldmatrix.sync.aligned.m8n8.x4.shared.b16 {%0,%1,%2,%3}, [%4];"
                 : "=r"(r[0]), "=r"(r[1]), "=r"(r[2]), "=r"(r[3]) : "r"(addr));
}

__device__ __forceinline__ void ldsm_x4_trans(uint32_t* r, uint32_t addr) {
    asm volatile("ldmatrix.sync.aligned.m8n8.x4.trans.shared.b16 {%0,%1,%2,%3}, [%4];"
                 : "=r"(r[0]), "=r"(r[1]), "=r"(r[2]), "=r"(r[3]) : "r"(addr));
}

__device__ __forceinline__ void mma16816(float* d, const uint32_t* a,
                                         const uint32_t* b) {
    asm volatile(
        "mma.sync.aligned.m16n8k16.row.col.f32.f16.f16.f32 "
        "{%0,%1,%2,%3}, {%4,%5,%6,%7}, {%8,%9}, {%0,%1,%2,%3};"
        : "+f"(d[0]), "+f"(d[1]), "+f"(d[2]), "+f"(d[3])
        : "r"(a[0]), "r"(a[1]), "r"(a[2]), "r"(a[3]), "r"(b[0]), "r"(b[1]));
}

#define CP_ASYNC16(dst_u32, src_ptr) \
    asm volatile("cp.async.cg.shared.global [%0], [%1], 16;" \
                 :: "r"(dst_u32), "l"(src_ptr))
#define CP_COMMIT() asm volatile("cp.async.commit_group;" ::: "memory")
#define CP_WAIT(n)  asm volatile("cp.async.wait_group %0;" :: "n"(n) : "memory")

__device__ __forceinline__ uint32_t pack_h2(float x, float y) {
    __half2 t = __floats2half2_rn(x, y);
    return *(uint32_t*)&t;
}

// ---------------------------------------------------------------------------
// ONE setup kernel: conversions + bias concat + rope trig tables.
// ---------------------------------------------------------------------------
#define CV_X  (M_ROWS * HDIM / 4)
#define CV_WQ (HDIM * HDIM / 4)
#define CV_WK (512 * HDIM / 4)
#define CV_B0 CV_X
#define CV_B1 (CV_B0 + CV_WQ)
#define CV_B2 (CV_B1 + CV_WK)
#define CV_B3 (CV_B2 + CV_WK)
#define CV_B4 (CV_B3 + CV_WQ)
#define CV_B5 (CV_B4 + (NQKV / 4))       // bias concat (768 f4)
#define CV_TOTAL (CV_B5 + M_ROWS * 64)   // + rope table entries (262144)

__device__ __forceinline__ void cvt4(const float* __restrict__ in,
                                     __half* __restrict__ out, int j)
{
    float4 v = ((const float4*)in)[j];
    ((__half2*)out)[2 * j]     = __floats2half2_rn(v.x, v.y);
    ((__half2*)out)[2 * j + 1] = __floats2half2_rn(v.z, v.w);
}

__global__ void setup_kernel(const float* __restrict__ hs,
                             const float* __restrict__ wq,
                             const float* __restrict__ wk,
                             const float* __restrict__ wv,
                             const float* __restrict__ wo,
                             const float* __restrict__ bq,
                             const float* __restrict__ bk,
                             const float* __restrict__ bv,
                             const int* __restrict__ pos_ids,
                             __half* __restrict__ x16,
                             __half* __restrict__ wqkv16,
                             __half* __restrict__ wo16,
                             float* __restrict__ bqkv,
                             float* __restrict__ rcos,
                             float* __restrict__ rsin)
{
    int i = blockIdx.x * 256 + threadIdx.x;
    if (i < CV_B0) {
        cvt4(hs, x16, i);
    } else if (i < CV_B1) {
        cvt4(wq, wqkv16, i - CV_B0);
    } else if (i < CV_B2) {
        cvt4(wk, wqkv16 + 2048 * HDIM, i - CV_B1);
    } else if (i < CV_B3) {
        cvt4(wv, wqkv16 + 2560 * HDIM, i - CV_B2);
    } else if (i < CV_B4) {
        cvt4(wo, wo16, i - CV_B3);
    } else if (i < CV_B5) {
        int j = i - CV_B4;               // 0..767 (f4 over 3072 floats)
        int e = j * 4;
        float4 v;
        if (e < 2048)        v = *(const float4*)(bq + e);
        else if (e < 2560)   v = *(const float4*)(bk + (e - 2048));
        else                 v = *(const float4*)(bv + (e - 2560));
        *(float4*)(bqkv + e) = v;
    } else if (i < CV_TOTAL) {
        int j  = i - CV_B5;              // 0..262143
        int pr = j & 63;
        int m  = j >> 6;                 // 0..4095
        int bb = m >> 11, ss = m & 2047;
        // identical expressions to the former in-epilogue computation
        float p   = (float)pos_ids[bb * S_LEN + ss];
        float inv = expf(-(float)pr * (13.815510557964274f / 64.0f));
        float ph  = p * inv;
        float c, sn;
        sincosf(ph, &sn, &c);
        rcos[j] = c;
        rsin[j] = sn;
    }
}

// ---------------------------------------------------------------------------
// GEMM core: block 128x128, BK=32, 4 warps (2m x 2n), warp tile 64x64,
// 128 threads, 3-stage cp.async pipeline. MMA:ldsm ratio 4.0.  (R12-proven)
// ---------------------------------------------------------------------------
#define MATB (128 * 80)              // 10240 B per matrix tile
#define STAGEB (2 * MATB)            // A + B = 20480 B
#define NSTAGE 3
#define EPI_STR 132                  // fp32 epilogue smem row stride (floats)
#define EPI_BYTES (128 * EPI_STR * 4)             // 67584
#define GEMM_SMEM (EPI_BYTES)        // >= NSTAGE*STAGEB (61440); epilogue reuse
#define GEMM_THREADS 128

__device__ __forceinline__ void gemm_copy_stage(
    uint32_t s_u32,
    const __half* __restrict__ Ap, const __half* __restrict__ Bp,
    int m0, int n0, int k0, int Kdim, int t)
{
#pragma unroll
    for (int i = 0; i < 4; i++) {
        int chunk = t + i * GEMM_THREADS;      // 0..511
        int row = chunk >> 2;
        int ch  = chunk & 3;
        uint32_t dst = s_u32 + row * 80 + ch * 16;
        size_t aoff = (size_t)(m0 + row) * Kdim + k0 + ch * 8;
        size_t boff = (size_t)(n0 + row) * Kdim + k0 + ch * 8;
        CP_ASYNC16(dst,        Ap + aoff);
        CP_ASYNC16(dst + MATB, Bp + boff);
    }
}

// Mainloop: fills acc[4][8][4] (warp tile 64x64).
__device__ __forceinline__ void gemm_mainloop(
    uint32_t s_u32, const __half* Ap, const __half* Bp,
    int m0, int n0, int Kdim, int t, int lane,
    int wm, int wn, float acc[4][8][4])
{
    const int nsteps = Kdim >> 5;
    const int a_row_l = lane & 15;
    const int a_col_l = (lane >> 4) * 8;
    const int b_row_l = ((lane >> 4) << 3) + (lane & 7);
    const int b_col_l = ((lane >> 3) & 1) * 8;

    // Prologue: stages 0, 1
    gemm_copy_stage(s_u32,          Ap, Bp, m0, n0, 0,  Kdim, t);
    CP_COMMIT();
    gemm_copy_stage(s_u32 + STAGEB, Ap, Bp, m0, n0, 32, Kdim, t);
    CP_COMMIT();

    int buf = 0;
    for (int s = 0; s < nsteps; s++) {
        if (s + 1 < nsteps) { CP_WAIT(1); } else { CP_WAIT(0); }
        __syncthreads();

        if (s + 2 < nsteps) {
            int nb = buf + 2; if (nb >= NSTAGE) nb -= NSTAGE;
            gemm_copy_stage(s_u32 + nb * STAGEB, Ap, Bp,
                            m0, n0, (s + 2) << 5, Kdim, t);
            CP_COMMIT();
        }

        uint32_t sA = s_u32 + buf * STAGEB;
        uint32_t sB = sA + MATB;

#pragma unroll
        for (int kh = 0; kh < 2; kh++) {
            uint32_t af[4][4], bf[4][4];
#pragma unroll
            for (int mt = 0; mt < 4; mt++) {
                uint32_t ad = sA + (wm + mt * 16 + a_row_l) * 80 +
                              (kh * 16 + a_col_l) * 2;
                ldsm_x4(af[mt], ad);
            }
#pragma unroll
            for (int np = 0; np < 4; np++) {
                uint32_t bd = sB + (wn + np * 16 + b_row_l) * 80 +
                              (kh * 16 + b_col_l) * 2;
                ldsm_x4(bf[np], bd);
            }
#pragma unroll
            for (int mt = 0; mt < 4; mt++) {
#pragma unroll
                for (int np = 0; np < 4; np++) {
                    mma16816(acc[mt][np * 2],     af[mt], &bf[np][0]);
                    mma16816(acc[mt][np * 2 + 1], af[mt], &bf[np][2]);
                }
            }
        }
        __syncthreads();
        buf++; if (buf == NSTAGE) buf = 0;
    }
}

// Fused QKV projection + RoPE (table-driven).
// N-regions: [0,2048)=Q (rope, scale, fp16), [2048,2560)=K (rope, fp16),
// [2560,3072)=V (fp16 direct). Each 128-col block = one head.
__global__ __launch_bounds__(GEMM_THREADS) void tc_gemm_qkv_kernel(
    const __half* __restrict__ Ap, const __half* __restrict__ Bp,
    const float* __restrict__ bias,
    const float* __restrict__ rcos, const float* __restrict__ rsin,
    __half* __restrict__ qout, __half* __restrict__ kout,
    __half* __restrict__ vout)
{
    extern __shared__ char smem[];
    const uint32_t s_u32 = smem_to_u32(smem);
    float* smf = (float*)smem;
    const int t    = threadIdx.x;
    const int wid  = t >> 5;
    const int lane = t & 31;
    const int m0   = blockIdx.y * 128;
    const int n0   = blockIdx.x * 128;
    const int wm   = (wid >> 1) * 64;
    const int wn   = (wid & 1) * 64;

    float acc[4][8][4];
#pragma unroll
    for (int a = 0; a < 4; a++)
#pragma unroll
        for (int b = 0; b < 8; b++)
#pragma unroll
            for (int c = 0; c < 4; c++) acc[a][b][c] = 0.0f;

    gemm_mainloop(s_u32, Ap, Bp, m0, n0, HDIM, t, lane, wm, wn, acc);

    const int er = lane >> 2;
    const int ec = (lane & 3) * 2;

    if (n0 >= 2560) {
        // V region -> fp16 head-major direct
#pragma unroll
        for (int mt = 0; mt < 4; mt++) {
#pragma unroll
            for (int nt = 0; nt < 8; nt++) {
                int mloc = wm + mt * 16 + er;
                int nloc = wn + nt * 8 + ec;
                int m = m0 + mloc;
                int n = n0 + nloc;
                int bb = m >> 11, ss = m & 2047;
                float bx = bias[n], by = bias[n + 1];
                float v00 = acc[mt][nt][0] + bx, v01 = acc[mt][nt][1] + by;
                float v10 = acc[mt][nt][2] + bx, v11 = acc[mt][nt][3] + by;
                int nn = n - 2560;
                int head = nn >> 7, d = nn & 127;
                __half* op = vout + (size_t)(((bb * NHKV + head) * S_LEN + ss) * HD + d);
                *(__half2*)op = __floats2half2_rn(v00, v01);
                *(__half2*)(op + 8 * HD) = __floats2half2_rn(v10, v11);
            }
        }
        return;
    }

    // Q or K region: stage acc+bias (fp32) into smem, then table-rope -> fp16.
#pragma unroll
    for (int mt = 0; mt < 4; mt++) {
#pragma unroll
        for (int nt = 0; nt < 8; nt++) {
            int mloc = wm + mt * 16 + er;
            int nloc = wn + nt * 8 + ec;
            int n = n0 + nloc;
            float bx = bias[n], by = bias[n + 1];
            float2 a; a.x = acc[mt][nt][0] + bx; a.y = acc[mt][nt][1] + by;
            float2 b; b.x = acc[mt][nt][2] + bx; b.y = acc[mt][nt][3] + by;
            *(float2*)(smf + mloc * EPI_STR + nloc) = a;
            *(float2*)(smf + (mloc + 8) * EPI_STR + nloc) = b;
        }
    }
    __syncthreads();

    const bool isQ = (n0 < 2048);
    const float scale = isQ ? 0.08838834764831845f : 1.0f;
    const int head = isQ ? (n0 >> 7) : ((n0 - 2048) >> 7);
    const int NH   = isQ ? NHQ : NHKV;
    __half* outp   = isQ ? qout : kout;

    // 128 rows x 64 pairs; 128 threads x 64 iterations.
#pragma unroll 4
    for (int i = 0; i < 64; i++) {
        int idx = t + i * 128;
        int row = idx >> 6;          // 0..127
        int pr  = idx & 63;          // pair index (d in [0,64))
        int m = m0 + row;
        int bb = m >> 11, ss = m & 2047;

        float c  = rcos[m * 64 + pr];
        float sn = rsin[m * 64 + pr];

        float x1 = smf[row * EPI_STR + pr];
        float x2 = smf[row * EPI_STR + pr + 64];
        float y1 = (x1 * c - x2 * sn) * scale;
        float y2 = (x2 * c + x1 * sn) * scale;

        size_t base = (size_t)(((bb * NH + head) * S_LEN + ss) * HD);
        outp[base + pr]      = __float2half_rn(y1);
        outp[base + 64 + pr] = __float2half_rn(y2);
    }
}

// O-projection: row-major fp32, no bias.
__global__ __launch_bounds__(GEMM_THREADS) void tc_gemm_o_kernel(
    const __half* __restrict__ Ap, const __half* __restrict__ Bp,
    float* __restrict__ out)
{
    extern __shared__ char smem[];
    const uint32_t s_u32 = smem_to_u32(smem);
    const int t    = threadIdx.x;
    const int wid  = t >> 5;
    const int lane = t & 31;
    const int m0   = blockIdx.y * 128;
    const int n0   = blockIdx.x * 128;
    const int wm   = (wid >> 1) * 64;
    const int wn   = (wid & 1) * 64;

    float acc[4][8][4];
#pragma unroll
    for (int a = 0; a < 4; a++)
#pragma unroll
        for (int b = 0; b < 8; b++)
#pragma unroll
            for (int c = 0; c < 4; c++) acc[a][b][c] = 0.0f;

    gemm_mainloop(s_u32, Ap, Bp, m0, n0, HDIM, t, lane, wm, wn, acc);

    const int er = lane >> 2;
    const int ec = (lane & 3) * 2;
#pragma unroll
    for (int mt = 0; mt < 4; mt++) {
#pragma unroll
        for (int nt = 0; nt < 8; nt++) {
            int mloc = wm + mt * 16 + er;
            int nloc = wn + nt * 8 + ec;
            int m = m0 + mloc;
            float* op = out + (size_t)m * HDIM + n0 + nloc;
            float2 a; a.x = acc[mt][nt][0]; a.y = acc[mt][nt][1];
            float2 b; b.x = acc[mt][nt][2]; b.y = acc[mt][nt][3];
            *(float2*)op = a;
            *(float2*)(op + 8 * HDIM) = b;
        }
    }
}

// ---------------------------------------------------------------------------
// Tensor-core flash attention, fp16, causal, GQA (unchanged, proven).
// BM=128, BN=64, 8 warps. V natural layout + ldmatrix.trans for PV.
// K/V tiles double-buffered with cp.async; heavy q-tiles first.
// ---------------------------------------------------------------------------
#define FQ_STR 136
#define FK_STR 136
#define SQ_OFF 0
#define KV_OFF (128 * FQ_STR)            // elems
#define KV_STAGE (2 * 64 * FK_STR)       // K tile + V tile per stage, elems
#define FLASH_SMEM_ELEMS (KV_OFF + 2 * KV_STAGE)
#define FLASH_SMEM_BYTES (FLASH_SMEM_ELEMS * 2)   // 104448 B

__device__ __forceinline__ void flash_load_kv(
    uint32_t s_u32, int stage_elems,
    const __half* __restrict__ Kp, const __half* __restrict__ Vp,
    int j, int t)
{
#pragma unroll
    for (int i = 0; i < 4; i++) {
        int chunk = t + i * 256;           // 0..1023
        int row = chunk >> 4;              // 0..63
        int cg  = chunk & 15;
        uint32_t kd = s_u32 + (stage_elems + row * FK_STR + cg * 8) * 2;
        uint32_t vd = kd + (64 * FK_STR) * 2;
        CP_ASYNC16(kd, Kp + (size_t)(j * 64 + row) * HD + cg * 8);
        CP_ASYNC16(vd, Vp + (size_t)(j * 64 + row) * HD + cg * 8);
    }
}

__global__ __launch_bounds__(256) void flash16_kernel(
    const __half* __restrict__ Qg, const __half* __restrict__ Kg,
    const __half* __restrict__ Vg, __half* __restrict__ Ag)
{
    extern __shared__ __align__(16) __half sb[];
    const uint32_t s_u32 = smem_to_u32(sb);

    const int iq = (int)gridDim.x - 1 - (int)blockIdx.x;
    const int h  = blockIdx.y;
    const int b  = blockIdx.z;
    const int hkv = h >> 2;
    const int q0 = iq * 128;
    const int t    = threadIdx.x;
    const int wid  = t >> 5;
    const int lane = t & 31;

    const __half* Qp = Qg + (size_t)((b * NHQ + h) * S_LEN + q0) * HD;
    const __half* Kp = Kg + (size_t)((b * NHKV + hkv) * S_LEN) * HD;
    const __half* Vp = Vg + (size_t)((b * NHKV + hkv) * S_LEN) * HD;

#pragma unroll
    for (int i = 0; i < 8; i++) {
        int chunk = t + i * 256;
        int row = chunk >> 4;
        int cg  = chunk & 15;
        CP_ASYNC16(s_u32 + (SQ_OFF + row * FQ_STR + cg * 8) * 2,
                   Qp + (size_t)row * HD + cg * 8);
    }
    flash_load_kv(s_u32, KV_OFF, Kp, Vp, 0, t);
    CP_COMMIT();

    float o[16][4];
#pragma unroll
    for (int f = 0; f < 16; f++)
#pragma unroll
        for (int e = 0; e < 4; e++) o[f][e] = 0.0f;
    float m0 = -1e30f, m1 = -1e30f, l0 = 0.0f, l1 = 0.0f;

    const int a_row_l = lane & 15;
    const int a_col_l = (lane >> 4) * 8;
    const int b_row_l = ((lane >> 4) << 3) + (lane & 7);
    const int b_col_l = ((lane >> 3) & 1) * 8;
    const int er = lane >> 2;
    const int ec = (lane & 3) * 2;
    const int r0g = q0 + wid * 16 + er;
    const int r1g = r0g + 8;

    const int ntiles = (iq + 1) * 2;

    for (int j = 0; j < ntiles; j++) {
        int buf = j & 1;
        if (j + 1 < ntiles) {
            flash_load_kv(s_u32, KV_OFF + (buf ^ 1) * KV_STAGE, Kp, Vp, j + 1, t);
            CP_COMMIT();
            CP_WAIT(1);
        } else {
            CP_WAIT(0);
        }
        __syncthreads();

        const int skv = KV_OFF + buf * KV_STAGE;      // K tile base (elems)
        const int sv  = skv + 64 * FK_STR;            // V tile base

        // S = Q K^T
        float c[8][4];
#pragma unroll
        for (int nf = 0; nf < 8; nf++)
#pragma unroll
            for (int e = 0; e < 4; e++) c[nf][e] = 0.0f;

#pragma unroll
        for (int kh = 0; kh < 8; kh++) {
            uint32_t ah[4];
            uint32_t ad = s_u32 + (SQ_OFF + (wid * 16 + a_row_l) * FQ_STR +
                                   kh * 16 + a_col_l) * 2;
            ldsm_x4(ah, ad);
#pragma unroll
            for (int np = 0; np < 4; np++) {
                uint32_t bh[4];
                uint32_t bd = s_u32 + (skv + (np * 16 + b_row_l) * FK_STR +
                                       kh * 16 + b_col_l) * 2;
                ldsm_x4(bh, bd);
                mma16816(c[np * 2],     ah, &bh[0]);
                mma16816(c[np * 2 + 1], ah, &bh[2]);
            }
        }

        // Causal mask
        if (j >= 2 * iq) {
#pragma unroll
            for (int nf = 0; nf < 8; nf++) {
#pragma unroll
                for (int d = 0; d < 2; d++) {
                    int col = j * 64 + nf * 8 + ec + d;
                    if (col > r0g) c[nf][d]     = -1e30f;
                    if (col > r1g) c[nf][2 + d] = -1e30f;
                }
            }
        }

        // Online softmax
        float mx0 = -1e30f, mx1 = -1e30f;
#pragma unroll
        for (int nf = 0; nf < 8; nf++) {
            mx0 = fmaxf(mx0, fmaxf(c[nf][0], c[nf][1]));
            mx1 = fmaxf(mx1, fmaxf(c[nf][2], c[nf][3]));
        }
        mx0 = fmaxf(mx0, __shfl_xor_sync(0xffffffffu, mx0, 1));
        mx0 = fmaxf(mx0, __shfl_xor_sync(0xffffffffu, mx0, 2));
        mx1 = fmaxf(mx1, __shfl_xor_sync(0xffffffffu, mx1, 1));
        mx1 = fmaxf(mx1, __shfl_xor_sync(0xffffffffu, mx1, 2));

        float nm0 = fmaxf(m0, mx0), nm1 = fmaxf(m1, mx1);
        float al0 = __expf(m0 - nm0), al1 = __expf(m1 - nm1);
        m0 = nm0; m1 = nm1;

        float s0 = 0.0f, s1 = 0.0f;
#pragma unroll
        for (int nf = 0; nf < 8; nf++) {
            c[nf][0] = __expf(c[nf][0] - nm0);
            c[nf][1] = __expf(c[nf][1] - nm0);
            c[nf][2] = __expf(c[nf][2] - nm1);
            c[nf][3] = __expf(c[nf][3] - nm1);
            s0 += c[nf][0] + c[nf][1];
            s1 += c[nf][2] + c[nf][3];
        }
        s0 += __shfl_xor_sync(0xffffffffu, s0, 1);
        s0 += __shfl_xor_sync(0xffffffffu, s0, 2);
        s1 += __shfl_xor_sync(0xffffffffu, s1, 1);
        s1 += __shfl_xor_sync(0xffffffffu, s1, 2);
        l0 = l0 * al0 + s0;
        l1 = l1 * al1 + s1;

#pragma unroll
        for (int f = 0; f < 16; f++) {
            o[f][0] *= al0; o[f][1] *= al0;
            o[f][2] *= al1; o[f][3] *= al1;
        }

        // P @ V with trans-loaded B fragments from natural V layout
#pragma unroll
        for (int kf = 0; kf < 4; kf++) {
            int nf0 = kf * 2, nf1 = kf * 2 + 1;
            uint32_t pa[4];
            pa[0] = pack_h2(c[nf0][0], c[nf0][1]);
            pa[1] = pack_h2(c[nf0][2], c[nf0][3]);
            pa[2] = pack_h2(c[nf1][0], c[nf1][1]);
            pa[3] = pack_h2(c[nf1][2], c[nf1][3]);
#pragma unroll
            for (int nt = 0; nt < 8; nt++) {
                uint32_t bv[4];
                uint32_t bd = s_u32 + (sv + (kf * 16 + (lane & 15)) * FK_STR +
                                       nt * 16 + (lane >> 4) * 8) * 2;
                ldsm_x4_trans(bv, bd);
                mma16816(o[nt * 2],     pa, &bv[0]);
                mma16816(o[nt * 2 + 1], pa, &bv[2]);
            }
        }
        __syncthreads();
    }

    // Epilogue: fp16 row-major [m, h*128 + d]
    float inv0 = 1.0f / l0, inv1 = 1.0f / l1;
    __half* Ap0 = Ag + (size_t)(b * S_LEN + r0g) * HDIM + h * HD;
    __half* Ap1 = Ag + (size_t)(b * S_LEN + r1g) * HDIM + h * HD;
#pragma unroll
    for (int f = 0; f < 16; f++) {
        int col = (f >> 1) * 16 + (f & 1) * 8 + ec;
        __half2 v0 = __floats2half2_rn(o[f][0] * inv0, o[f][1] * inv0);
        __half2 v1 = __floats2half2_rn(o[f][2] * inv1, o[f][3] * inv1);
        *(__half2*)(Ap0 + col) = v0;
        *(__half2*)(Ap1 + col) = v1;
    }
}

// ---------------------------------------------------------------------------
// Launch
// ---------------------------------------------------------------------------
extern "C" void kernel_launch(void* const* d_in, const int* in_sizes, int n_in,
                              void* d_out, int out_size)
{
    const float* hs = (const float*)d_in[0];
    const float* wq = (const float*)d_in[1];
    const float* bq = (const float*)d_in[2];
    const float* wk = (const float*)d_in[3];
    const float* bk = (const float*)d_in[4];
    const float* wv = (const float*)d_in[5];
    const float* bv = (const float*)d_in[6];
    const float* wo = (const float*)d_in[7];
    const int*  pos = (const int*)d_in[8];
    float* out = (float*)d_out;

    float *bqkv, *rcos, *rsin;
    cudaGetSymbolAddress((void**)&bqkv, g_bqkv);
    cudaGetSymbolAddress((void**)&rcos, g_rcos);
    cudaGetSymbolAddress((void**)&rsin, g_rsin);

    __half *x16, *wqkv16, *wo16, *qh16, *kh16, *vh16, *a16;
    cudaGetSymbolAddress((void**)&x16,    g_x16);
    cudaGetSymbolAddress((void**)&wqkv16, g_wqkv16);
    cudaGetSymbolAddress((void**)&wo16,   g_wo16);
    cudaGetSymbolAddress((void**)&qh16,   g_qh16);
    cudaGetSymbolAddress((void**)&kh16,   g_kh16);
    cudaGetSymbolAddress((void**)&vh16,   g_vh16);
    cudaGetSymbolAddress((void**)&a16,    g_a16);

    cudaFuncSetAttribute(flash16_kernel,
                         cudaFuncAttributeMaxDynamicSharedMemorySize, FLASH_SMEM_BYTES);
    cudaFuncSetAttribute(tc_gemm_qkv_kernel,
                         cudaFuncAttributeMaxDynamicSharedMemorySize, GEMM_SMEM);
    cudaFuncSetAttribute(tc_gemm_o_kernel,
                         cudaFuncAttributeMaxDynamicSharedMemorySize, GEMM_SMEM);

    // 1. ONE setup kernel: conversions + bias concat + rope tables
    setup_kernel<<<(CV_TOTAL + 255) / 256, 256>>>(
        hs, wq, wk, wv, wo, bq, bk, bv, pos, x16, wqkv16, wo16, bqkv, rcos, rsin);

    // 2. Fused QKV projection + table-RoPE (768 CTAs, 128 threads each)
    tc_gemm_qkv_kernel<<<dim3(NQKV / 128, M_ROWS / 128), GEMM_THREADS, GEMM_SMEM>>>(
        x16, wqkv16, bqkv, rcos, rsin, qh16, kh16, vh16);

    // 3. Flash attention (fp16 MMA), heavy tiles first
    flash16_kernel<<<dim3(S_LEN / 128, NHQ, BATCH), 256, FLASH_SMEM_BYTES>>>(
        qh16, kh16, vh16, a16);

    // 4. O-projection -> d_out (row-major fp32)
    tc_gemm_o_kernel<<<dim3(HDIM / 128, M_ROWS / 128), GEMM_THREADS, GEMM_SMEM>>>(
        a16, wo16, out);
}